// round 12
// baseline (speedup 1.0000x reference)
#include <cuda_runtime.h>
#include <cuda_bf16.h>
#include <cuda_fp16.h>
#include <mma.h>
#include <math.h>
#include <stddef.h>
#include <stdint.h>

using namespace nvcuda;
typedef unsigned long long ull;

#define BATCH 512
#define TT    256
#define IIN   64
#define HH    256
#define MTOT  (BATCH * TT)          // 131072 rows for x_proj GEMMs

// GEMM staging
#define LDT        72               // padded smem ld (bf16 elems)
#define GEMM_SMEM  (4 * 128 * LDT * 2)      // 73728 B

// TC recurrence: 32 CTAs x 16 batches, 512 threads (16 warps x 64 N-cols)
#define MB       16
#define NCTA     (BATCH / MB)       // 32
#define RTHR     512
// smem: A   [16 m][264 k] half   =  8448 B
//       scr [16 m][1044 n] f32   = 66816 B
//       bias[1032] f32           =  4128 B
#define A_OFF       0
#define A_BYTES     (16 * 264 * 2)
#define SCR_OFF     (A_OFF + A_BYTES)
#define SCR_BYTES   (16 * 1044 * 4)
#define BIA_OFF     (SCR_OFF + SCR_BYTES)
#define REC_SMEM    (BIA_OFF + 1032 * 4)    // 79392 B

// ---------------- static device scratch ------------------------------------
__device__ __nv_bfloat16 g_xhi[(size_t)MTOT * IIN];
__device__ __nv_bfloat16 g_xlo[(size_t)MTOT * IIN];
__device__ __nv_bfloat16 g_w0hi[4 * HH * IIN];
__device__ __nv_bfloat16 g_w0lo[4 * HH * IIN];
__device__ __nv_bfloat16 g_w1hi[4 * HH * HH];
__device__ __nv_bfloat16 g_w1lo[4 * HH * HH];
__device__ __nv_bfloat16 g_h1hi[(size_t)MTOT * HH];
__device__ __nv_bfloat16 g_h1lo[(size_t)MTOT * HH];
__device__ float  g_xp[(size_t)4 * MTOT * HH];    // [4][MTOT][256] gate-major
__device__ __half g_w2_0[HH * 4 * HH];            // k-major W^T [256][1024]
__device__ __half g_w2_1[HH * 4 * HH];
__device__ float  g_bias0[4 * HH];
__device__ float  g_bias1[4 * HH];
__device__ float  g_h2last[BATCH * HH];

__device__ __forceinline__ float tanh_ap(float x) {
    float y;
    asm("tanh.approx.f32 %0, %1;" : "=f"(y) : "f"(x));
    return y;
}
__device__ __forceinline__ float sig_ap(float x) {
    return 0.5f * tanh_ap(0.5f * x) + 0.5f;
}

// ---------------- conversions & packing ------------------------------------
__global__ void cvt_pair_kernel(const float* __restrict__ src,
                                __nv_bfloat16* __restrict__ hi,
                                __nv_bfloat16* __restrict__ lo, size_t n)
{
    for (size_t i = (size_t)blockIdx.x * blockDim.x + threadIdx.x; i < n;
         i += (size_t)gridDim.x * blockDim.x) {
        float v = src[i];
        __nv_bfloat16 h = __float2bfloat16(v);
        hi[i] = h;
        lo[i] = __float2bfloat16(v - __bfloat162float(h));
    }
}

// w_hh [1024 n][256 k] fp32 -> w2 [256 k][1024 n] fp16 (= W^T, k-major)
__global__ void pack_whh_tc(const float* __restrict__ w_hh,
                            const float* __restrict__ b_ih,
                            const float* __restrict__ b_hh,
                            __half* __restrict__ w2,
                            float* __restrict__ bp)
{
    for (int idx = blockIdx.x * blockDim.x + threadIdx.x; idx < 4 * HH * HH;
         idx += gridDim.x * blockDim.x) {
        int n = idx & 1023;
        int k = idx >> 10;
        w2[idx] = __float2half(w_hh[(size_t)n * HH + k]);
    }
    for (int r = blockIdx.x * blockDim.x + threadIdx.x; r < 4 * HH;
         r += gridDim.x * blockDim.x)
        bp[r] = b_ih[r] + b_hh[r];
}

// ---------------- x_proj GEMM: smem-staged HMMA (bf16 hi/lo 3-term) ----------
template <int K>
__global__ __launch_bounds__(256, 1)
void gemm_xproj_smem(const __nv_bfloat16* __restrict__ Ahi,
                     const __nv_bfloat16* __restrict__ Alo,
                     const __nv_bfloat16* __restrict__ Bhi,
                     const __nv_bfloat16* __restrict__ Blo,
                     float* __restrict__ xp)
{
    extern __shared__ __align__(16) __nv_bfloat16 sm[];
    __nv_bfloat16* sAhi = sm;
    __nv_bfloat16* sAlo = sm + 128 * LDT;
    __nv_bfloat16* sBhi = sm + 2 * 128 * LDT;
    __nv_bfloat16* sBlo = sm + 3 * 128 * LDT;

    const int tid = threadIdx.x;
    const int w   = tid >> 5;
    const int wm  = w & 3, wn = w >> 2;
    const size_t mBase = (size_t)blockIdx.x * 128;
    const int    nBase = blockIdx.y * 128;

    wmma::fragment<wmma::accumulator, 16, 16, 16, float> acc[2][4];
#pragma unroll
    for (int i = 0; i < 2; ++i)
#pragma unroll
        for (int f = 0; f < 4; ++f) wmma::fill_fragment(acc[i][f], 0.0f);

    for (int kc = 0; kc < K; kc += 64) {
        if (kc) __syncthreads();
        for (int i = tid; i < 1024; i += 256) {
            int row = i >> 3;
            int col = (i & 7) * 8;
            size_t ga = (mBase + row) * K + kc + col;
            size_t gb = ((size_t)(nBase + row)) * K + kc + col;
            *(uint4*)(sAhi + row * LDT + col) = *(const uint4*)(Ahi + ga);
            *(uint4*)(sAlo + row * LDT + col) = *(const uint4*)(Alo + ga);
            *(uint4*)(sBhi + row * LDT + col) = *(const uint4*)(Bhi + gb);
            *(uint4*)(sBlo + row * LDT + col) = *(const uint4*)(Blo + gb);
        }
        __syncthreads();

#pragma unroll
        for (int term = 0; term < 3; ++term) {
            const __nv_bfloat16* A = (term == 1) ? sAlo : sAhi;
            const __nv_bfloat16* B = (term == 2) ? sBlo : sBhi;
#pragma unroll
            for (int k0 = 0; k0 < 64; k0 += 16) {
                wmma::fragment<wmma::matrix_a, 16, 16, 16, __nv_bfloat16,
                               wmma::row_major> fa[2];
                wmma::load_matrix_sync(fa[0], A + (wm * 32) * LDT + k0, LDT);
                wmma::load_matrix_sync(fa[1], A + (wm * 32 + 16) * LDT + k0, LDT);
#pragma unroll
                for (int f = 0; f < 4; ++f) {
                    wmma::fragment<wmma::matrix_b, 16, 16, 16, __nv_bfloat16,
                                   wmma::col_major> fb;
                    wmma::load_matrix_sync(fb, B + (wn * 64 + f * 16) * LDT + k0,
                                           LDT);
                    wmma::mma_sync(acc[0][f], fa[0], fb, acc[0][f]);
                    wmma::mma_sync(acc[1][f], fa[1], fb, acc[1][f]);
                }
            }
        }
    }

    const size_t m0 = mBase + wm * 32;
    const int    n0 = nBase + wn * 64;
#pragma unroll
    for (int i = 0; i < 2; ++i)
#pragma unroll
        for (int f = 0; f < 4; ++f) {
            int c0 = n0 + f * 16;
            int g = c0 >> 8, j0 = c0 & 255;
            float* dst = xp + ((size_t)g * MTOT + m0 + i * 16) * HH + j0;
            wmma::store_matrix_sync(dst, acc[i][f], HH, wmma::mem_row_major);
        }
}

// ---------------- tensor-core recurrence (single CTA, direct-L2 weights) -----
// 32 CTAs x 16 batches. Per step: gates[16,1024] = A[16,256]@W^T via wmma fp16.
// Weight fragments load DIRECTLY from global (L2-resident 512KB, re-read each
// step) — no smem staging, halving L1/smem traffic vs cp.async staging.
template <bool STORE_PAIR>
__global__ __launch_bounds__(RTHR, 1)
void lstm_rec_tc(const float* __restrict__ xp,    // [4][MTOT][256]
                 const __half* __restrict__ w2,   // [256][1024] k-major
                 const float* __restrict__ bp,    // [1024]
                 __nv_bfloat16* __restrict__ ohi,
                 __nv_bfloat16* __restrict__ olo,
                 float* __restrict__ olast)       // [BATCH][HH]
{
    extern __shared__ __align__(16) char dsm[];
    __half* Ah    = (__half*)(dsm + A_OFF);       // [16][264]
    float*  scr   = (float*)(dsm + SCR_OFF);      // [16][1044]
    float*  sbias = (float*)(dsm + BIA_OFF);      // [1024]

    const int tid  = threadIdx.x;
    const int wid  = tid >> 5;
    const int lane = tid & 31;
    const int n0   = wid * 64;                    // warp's N-column base
    const int b    = wid;                         // epilogue batch == warp id
    const int j0e  = lane * 8;                    // epilogue j base (8 j's)
    const int b0c  = blockIdx.x * MB;

    // init: A = 0, bias -> smem
    for (int i = tid; i < 16 * 264; i += RTHR) Ah[i] = __float2half(0.0f);
    for (int i = tid; i < 1024; i += RTHR) sbias[i] = bp[i];

    float c8[8];
#pragma unroll
    for (int v = 0; v < 8; ++v) c8[v] = 0.0f;

    __syncthreads();

    for (int t = 0; t < TT; ++t) {
        const size_t m = (size_t)(b0c + b) * TT + t;

        // prefetch xp for this thread's (b, j0e..j0e+8) — consumed after BAR_A
        float4 xg[4][2];
#pragma unroll
        for (int g = 0; g < 4; ++g) {
            const float* base = xp + ((size_t)g * MTOT + m) * HH + j0e;
            xg[g][0] = __ldg((const float4*)base);
            xg[g][1] = __ldg((const float4*)(base + 4));
        }

        // ---- MMA phase: 16 k-chunks, fb straight from global (L2) ----
        wmma::fragment<wmma::accumulator, 16, 16, 16, float> acc[4];
#pragma unroll
        for (int f = 0; f < 4; ++f) wmma::fill_fragment(acc[f], 0.0f);

#pragma unroll 4
        for (int kc = 0; kc < 16; ++kc) {
            wmma::fragment<wmma::matrix_a, 16, 16, 16, __half,
                           wmma::row_major> fa;
            wmma::load_matrix_sync(fa, Ah + kc * 16, 264);
            const __half* wb = w2 + (size_t)(kc * 16) * 1024 + n0;
#pragma unroll
            for (int f = 0; f < 4; ++f) {
                wmma::fragment<wmma::matrix_b, 16, 16, 16, __half,
                               wmma::row_major> fb;
                wmma::load_matrix_sync(fb, wb + f * 16, 1024);
                wmma::mma_sync(acc[f], fa, fb, acc[f]);
            }
        }

        // acc -> scratch
#pragma unroll
        for (int f = 0; f < 4; ++f)
            wmma::store_matrix_sync(scr + n0 + f * 16, acc[f], 1044,
                                    wmma::mem_row_major);
        __syncthreads();                          // BAR_A

        // ---- state update: thread owns (batch b, j0e..j0e+7) ----
        float G[4][8];
#pragma unroll
        for (int g = 0; g < 4; ++g) {
            const float* sp = scr + b * 1044 + g * 256 + j0e;
            float4 s0 = *(const float4*)sp;
            float4 s1 = *(const float4*)(sp + 4);
            float4 bb0 = *(const float4*)(sbias + g * 256 + j0e);
            float4 bb1 = *(const float4*)(sbias + g * 256 + j0e + 4);
            G[g][0] = s0.x + bb0.x + xg[g][0].x;
            G[g][1] = s0.y + bb0.y + xg[g][0].y;
            G[g][2] = s0.z + bb0.z + xg[g][0].z;
            G[g][3] = s0.w + bb0.w + xg[g][0].w;
            G[g][4] = s1.x + bb1.x + xg[g][1].x;
            G[g][5] = s1.y + bb1.y + xg[g][1].y;
            G[g][6] = s1.z + bb1.z + xg[g][1].z;
            G[g][7] = s1.w + bb1.w + xg[g][1].w;
        }

        float hv[8];
#pragma unroll
        for (int v = 0; v < 8; ++v) {
            float iv = sig_ap(G[0][v]);
            float fv = sig_ap(G[1][v]);
            float gv = tanh_ap(G[2][v]);
            float ov = sig_ap(G[3][v]);
            c8[v] = fv * c8[v] + iv * gv;
            hv[v] = ov * tanh_ap(c8[v]);
        }

        // h -> A smem (fp16)
        {
            __half2 p0 = __floats2half2_rn(hv[0], hv[1]);
            __half2 p1 = __floats2half2_rn(hv[2], hv[3]);
            __half2 p2 = __floats2half2_rn(hv[4], hv[5]);
            __half2 p3 = __floats2half2_rn(hv[6], hv[7]);
            uint4 pk = make_uint4(*(uint32_t*)&p0, *(uint32_t*)&p1,
                                  *(uint32_t*)&p2, *(uint32_t*)&p3);
            *(uint4*)&Ah[b * 264 + j0e] = pk;
        }

        // outputs
        if (STORE_PAIR) {
            __nv_bfloat162 h0 = __float22bfloat162_rn(make_float2(hv[0], hv[1]));
            __nv_bfloat162 h1 = __float22bfloat162_rn(make_float2(hv[2], hv[3]));
            __nv_bfloat162 h2 = __float22bfloat162_rn(make_float2(hv[4], hv[5]));
            __nv_bfloat162 h3 = __float22bfloat162_rn(make_float2(hv[6], hv[7]));
            float l[8];
            l[0] = hv[0] - __bfloat162float(__low2bfloat16(h0));
            l[1] = hv[1] - __bfloat162float(__high2bfloat16(h0));
            l[2] = hv[2] - __bfloat162float(__low2bfloat16(h1));
            l[3] = hv[3] - __bfloat162float(__high2bfloat16(h1));
            l[4] = hv[4] - __bfloat162float(__low2bfloat16(h2));
            l[5] = hv[5] - __bfloat162float(__high2bfloat16(h2));
            l[6] = hv[6] - __bfloat162float(__low2bfloat16(h3));
            l[7] = hv[7] - __bfloat162float(__high2bfloat16(h3));
            __nv_bfloat162 l0 = __float22bfloat162_rn(make_float2(l[0], l[1]));
            __nv_bfloat162 l1 = __float22bfloat162_rn(make_float2(l[2], l[3]));
            __nv_bfloat162 l2 = __float22bfloat162_rn(make_float2(l[4], l[5]));
            __nv_bfloat162 l3 = __float22bfloat162_rn(make_float2(l[6], l[7]));
            *(uint4*)&ohi[m * HH + j0e] =
                make_uint4(*(uint32_t*)&h0, *(uint32_t*)&h1,
                           *(uint32_t*)&h2, *(uint32_t*)&h3);
            *(uint4*)&olo[m * HH + j0e] =
                make_uint4(*(uint32_t*)&l0, *(uint32_t*)&l1,
                           *(uint32_t*)&l2, *(uint32_t*)&l3);
        } else if (t == TT - 1) {
            float* dst = olast + (size_t)(b0c + b) * HH + j0e;
            *(float4*)dst = make_float4(hv[0], hv[1], hv[2], hv[3]);
            *(float4*)(dst + 4) = make_float4(hv[4], hv[5], hv[6], hv[7]);
        }
        __syncthreads();                          // BAR_B
    }
}

// ---------------- LayerNorm + exact GELU + linear head ----------------------
__device__ __forceinline__ float block_sum_256(float v, float* red)
{
    __syncthreads();
#pragma unroll
    for (int o = 16; o > 0; o >>= 1) v += __shfl_down_sync(0xffffffffu, v, o);
    if ((threadIdx.x & 31) == 0) red[threadIdx.x >> 5] = v;
    __syncthreads();
    if (threadIdx.x < 8) {
        v = red[threadIdx.x];
#pragma unroll
        for (int o = 4; o > 0; o >>= 1) v += __shfl_down_sync(0xffu, v, o);
        if (threadIdx.x == 0) red[0] = v;
    }
    __syncthreads();
    return red[0];
}

__global__ __launch_bounds__(HH)
void head_kernel(const float* __restrict__ h2,
                 const float* __restrict__ gamma,
                 const float* __restrict__ beta,
                 const float* __restrict__ hw,
                 const float* __restrict__ hb,
                 float* __restrict__ outp)
{
    __shared__ float red[8];
    const int b = blockIdx.x;
    const int tid = threadIdx.x;

    float v  = h2[(size_t)b * HH + tid];
    float mu = block_sum_256(v, red) * (1.0f / HH);
    float d  = v - mu;
    float var = block_sum_256(d * d, red) * (1.0f / HH);
    float y  = d * rsqrtf(var + 1e-5f) * gamma[tid] + beta[tid];
    float gl = 0.5f * y * (1.0f + erff(y * 0.70710678118654752440f));
    float s  = block_sum_256(gl * hw[tid], red);
    if (tid == 0) outp[b] = s + hb[0];
}

// ---------------- launch ----------------------------------------------------
extern "C" void kernel_launch(void* const* d_in, const int* in_sizes, int n_in,
                              void* d_out, int out_size)
{
    (void)in_sizes; (void)n_in; (void)out_size;

    const float* x     = (const float*)d_in[0];
    const float* w_ih0 = (const float*)d_in[1];
    const float* w_hh0 = (const float*)d_in[2];
    const float* b_ih0 = (const float*)d_in[3];
    const float* b_hh0 = (const float*)d_in[4];
    const float* w_ih1 = (const float*)d_in[5];
    const float* w_hh1 = (const float*)d_in[6];
    const float* b_ih1 = (const float*)d_in[7];
    const float* b_hh1 = (const float*)d_in[8];
    const float* ln_g  = (const float*)d_in[9];
    const float* ln_b  = (const float*)d_in[10];
    const float* hw    = (const float*)d_in[11];
    const float* hb    = (const float*)d_in[12];
    float* outp = (float*)d_out;

    __nv_bfloat16 *xhi, *xlo, *w0hi, *w0lo, *w1hi, *w1lo, *h1hi, *h1lo;
    __half *w20, *w21;
    float *xp, *bp0, *bp1, *h2l;
    cudaGetSymbolAddress((void**)&xhi,  g_xhi);
    cudaGetSymbolAddress((void**)&xlo,  g_xlo);
    cudaGetSymbolAddress((void**)&w0hi, g_w0hi);
    cudaGetSymbolAddress((void**)&w0lo, g_w0lo);
    cudaGetSymbolAddress((void**)&w1hi, g_w1hi);
    cudaGetSymbolAddress((void**)&w1lo, g_w1lo);
    cudaGetSymbolAddress((void**)&h1hi, g_h1hi);
    cudaGetSymbolAddress((void**)&h1lo, g_h1lo);
    cudaGetSymbolAddress((void**)&xp,   g_xp);
    cudaGetSymbolAddress((void**)&w20,  g_w2_0);
    cudaGetSymbolAddress((void**)&w21,  g_w2_1);
    cudaGetSymbolAddress((void**)&bp0,  g_bias0);
    cudaGetSymbolAddress((void**)&bp1,  g_bias1);
    cudaGetSymbolAddress((void**)&h2l,  g_h2last);

    cudaFuncSetAttribute(gemm_xproj_smem<IIN>,
                         cudaFuncAttributeMaxDynamicSharedMemorySize, GEMM_SMEM);
    cudaFuncSetAttribute(gemm_xproj_smem<HH>,
                         cudaFuncAttributeMaxDynamicSharedMemorySize, GEMM_SMEM);
    cudaFuncSetAttribute(lstm_rec_tc<true>,
                         cudaFuncAttributeMaxDynamicSharedMemorySize, REC_SMEM);
    cudaFuncSetAttribute(lstm_rec_tc<false>,
                         cudaFuncAttributeMaxDynamicSharedMemorySize, REC_SMEM);

    cvt_pair_kernel<<<512, 256>>>(x,     xhi,  xlo,  (size_t)MTOT * IIN);
    cvt_pair_kernel<<<128, 256>>>(w_ih0, w0hi, w0lo, (size_t)4 * HH * IIN);
    pack_whh_tc<<<256, 256>>>(w_hh0, b_ih0, b_hh0, w20, bp0);
    pack_whh_tc<<<256, 256>>>(w_hh1, b_ih1, b_hh1, w21, bp1);

    // layer 0
    gemm_xproj_smem<IIN><<<dim3(MTOT / 128, 8), 256, GEMM_SMEM>>>(
        xhi, xlo, w0hi, w0lo, xp);
    lstm_rec_tc<true><<<NCTA, RTHR, REC_SMEM>>>(xp, w20, bp0,
                                                h1hi, h1lo, nullptr);

    // layer 1
    cvt_pair_kernel<<<256, 256>>>(w_ih1, w1hi, w1lo, (size_t)4 * HH * HH);
    gemm_xproj_smem<HH><<<dim3(MTOT / 128, 8), 256, GEMM_SMEM>>>(
        h1hi, h1lo, w1hi, w1lo, xp);
    lstm_rec_tc<false><<<NCTA, RTHR, REC_SMEM>>>(xp, w21, bp1,
                                                 nullptr, nullptr, h2l);

    head_kernel<<<BATCH, HH>>>(h2l, ln_g, ln_b, hw, hb, outp);
}

// round 14
// speedup vs baseline: 2.0301x; 2.0301x over previous
#include <cuda_runtime.h>
#include <cuda_bf16.h>
#include <cuda_fp16.h>
#include <mma.h>
#include <math.h>
#include <stddef.h>
#include <stdint.h>

using namespace nvcuda;
typedef unsigned long long ull;

#define BATCH 512
#define TT    256
#define IIN   64
#define HH    256
#define MTOT  (BATCH * TT)          // 131072 rows for x_proj GEMMs

// GEMM staging
#define LDT        72               // padded smem ld (bf16 elems)
#define GEMM_SMEM  (4 * 128 * LDT * 2)      // 73728 B

// TC recurrence: 32 clusters x 2 CTAs; CTA: 16 batches x 512 gate-cols
#define MB       16
#define NCTA     64                 // 32 clusters * 2
#define RTHR     512
// dynamic smem layout (per CTA):
//   stage [16 warps][2 buf][16 k][72 n] half = 73728 B (data 32 n, pad->72)
//   Ah    [2 buf][16 m][264 k] half          = 16896 B
//   scr   [16 m][516 n] f32                  = 33024 B
//   bias  [512] f32                          =  2048 B
#define STG_OFF     0
#define AH_OFF      73728
#define SCR_OFF     90624
#define BIA_OFF     123648
#define REC_SMEM    125696

// ---------------- static device scratch ------------------------------------
__device__ __nv_bfloat16 g_xhi[(size_t)MTOT * IIN];
__device__ __nv_bfloat16 g_xlo[(size_t)MTOT * IIN];
__device__ __nv_bfloat16 g_w0hi[4 * HH * IIN];
__device__ __nv_bfloat16 g_w0lo[4 * HH * IIN];
__device__ __nv_bfloat16 g_w1hi[4 * HH * HH];
__device__ __nv_bfloat16 g_w1lo[4 * HH * HH];
__device__ __nv_bfloat16 g_h1hi[(size_t)MTOT * HH];
__device__ __nv_bfloat16 g_h1lo[(size_t)MTOT * HH];
__device__ float  g_xp[(size_t)4 * MTOT * HH];    // [4][MTOT][256] gate-major
__device__ __half g_w2_0[HH * 4 * HH];   // permuted k-major W^T [256][1024]
__device__ __half g_w2_1[HH * 4 * HH];
__device__ float  g_bias0[4 * HH];
__device__ float  g_bias1[4 * HH];
__device__ float  g_h2last[BATCH * HH];

__device__ __forceinline__ float tanh_ap(float x) {
    float y;
    asm("tanh.approx.f32 %0, %1;" : "=f"(y) : "f"(x));
    return y;
}
__device__ __forceinline__ float sig_ap(float x) {
    return 0.5f * tanh_ap(0.5f * x) + 0.5f;
}

// ---------------- conversions & packing ------------------------------------
__global__ void cvt_pair_kernel(const float* __restrict__ src,
                                __nv_bfloat16* __restrict__ hi,
                                __nv_bfloat16* __restrict__ lo, size_t n)
{
    for (size_t i = (size_t)blockIdx.x * blockDim.x + threadIdx.x; i < n;
         i += (size_t)gridDim.x * blockDim.x) {
        float v = src[i];
        __nv_bfloat16 h = __float2bfloat16(v);
        hi[i] = h;
        lo[i] = __float2bfloat16(v - __bfloat162float(h));
    }
}

// w_hh [1024 n][256 k] fp32 -> w2 [256 k][1024 p] fp16, column-PERMUTED:
// packed col p: r = p>>9, g = (p>>7)&3, jl = p&127  ->  orig n = g*256+r*128+jl
// so cluster-CTA rank r reads the contiguous halves [r*512, r*512+512).
__global__ void pack_whh_tc(const float* __restrict__ w_hh,
                            const float* __restrict__ b_ih,
                            const float* __restrict__ b_hh,
                            __half* __restrict__ w2,
                            float* __restrict__ bp)
{
    for (int idx = blockIdx.x * blockDim.x + threadIdx.x; idx < 4 * HH * HH;
         idx += gridDim.x * blockDim.x) {
        int p = idx & 1023;
        int k = idx >> 10;
        int r  = p >> 9;
        int g  = (p >> 7) & 3;
        int jl = p & 127;
        int n  = g * 256 + r * 128 + jl;
        w2[idx] = __float2half(w_hh[(size_t)n * HH + k]);
    }
    for (int r = blockIdx.x * blockDim.x + threadIdx.x; r < 4 * HH;
         r += gridDim.x * blockDim.x)
        bp[r] = b_ih[r] + b_hh[r];
}

// ---------------- x_proj GEMM: smem-staged HMMA (bf16 hi/lo 3-term) ----------
template <int K>
__global__ __launch_bounds__(256, 1)
void gemm_xproj_smem(const __nv_bfloat16* __restrict__ Ahi,
                     const __nv_bfloat16* __restrict__ Alo,
                     const __nv_bfloat16* __restrict__ Bhi,
                     const __nv_bfloat16* __restrict__ Blo,
                     float* __restrict__ xp)
{
    extern __shared__ __align__(16) __nv_bfloat16 sm[];
    __nv_bfloat16* sAhi = sm;
    __nv_bfloat16* sAlo = sm + 128 * LDT;
    __nv_bfloat16* sBhi = sm + 2 * 128 * LDT;
    __nv_bfloat16* sBlo = sm + 3 * 128 * LDT;

    const int tid = threadIdx.x;
    const int w   = tid >> 5;
    const int wm  = w & 3, wn = w >> 2;
    const size_t mBase = (size_t)blockIdx.x * 128;
    const int    nBase = blockIdx.y * 128;

    wmma::fragment<wmma::accumulator, 16, 16, 16, float> acc[2][4];
#pragma unroll
    for (int i = 0; i < 2; ++i)
#pragma unroll
        for (int f = 0; f < 4; ++f) wmma::fill_fragment(acc[i][f], 0.0f);

    for (int kc = 0; kc < K; kc += 64) {
        if (kc) __syncthreads();
        for (int i = tid; i < 1024; i += 256) {
            int row = i >> 3;
            int col = (i & 7) * 8;
            size_t ga = (mBase + row) * K + kc + col;
            size_t gb = ((size_t)(nBase + row)) * K + kc + col;
            *(uint4*)(sAhi + row * LDT + col) = *(const uint4*)(Ahi + ga);
            *(uint4*)(sAlo + row * LDT + col) = *(const uint4*)(Alo + ga);
            *(uint4*)(sBhi + row * LDT + col) = *(const uint4*)(Bhi + gb);
            *(uint4*)(sBlo + row * LDT + col) = *(const uint4*)(Blo + gb);
        }
        __syncthreads();

#pragma unroll
        for (int term = 0; term < 3; ++term) {
            const __nv_bfloat16* A = (term == 1) ? sAlo : sAhi;
            const __nv_bfloat16* B = (term == 2) ? sBlo : sBhi;
#pragma unroll
            for (int k0 = 0; k0 < 64; k0 += 16) {
                wmma::fragment<wmma::matrix_a, 16, 16, 16, __nv_bfloat16,
                               wmma::row_major> fa[2];
                wmma::load_matrix_sync(fa[0], A + (wm * 32) * LDT + k0, LDT);
                wmma::load_matrix_sync(fa[1], A + (wm * 32 + 16) * LDT + k0, LDT);
#pragma unroll
                for (int f = 0; f < 4; ++f) {
                    wmma::fragment<wmma::matrix_b, 16, 16, 16, __nv_bfloat16,
                                   wmma::col_major> fb;
                    wmma::load_matrix_sync(fb, B + (wn * 64 + f * 16) * LDT + k0,
                                           LDT);
                    wmma::mma_sync(acc[0][f], fa[0], fb, acc[0][f]);
                    wmma::mma_sync(acc[1][f], fa[1], fb, acc[1][f]);
                }
            }
        }
    }

    const size_t m0 = mBase + wm * 32;
    const int    n0 = nBase + wn * 64;
#pragma unroll
    for (int i = 0; i < 2; ++i)
#pragma unroll
        for (int f = 0; f < 4; ++f) {
            int c0 = n0 + f * 16;
            int g = c0 >> 8, j0 = c0 & 255;
            float* dst = xp + ((size_t)g * MTOT + m0 + i * 16) * HH + j0;
            wmma::store_matrix_sync(dst, acc[i][f], HH, wmma::mem_row_major);
        }
}

// ---------------- tensor-core recurrence: 2-CTA cluster N-split --------------
// 32 clusters x 2 CTAs; cluster owns 16 batches. CTA rank r owns j-slice
// [128r,128r+128) of all 4 gates (512 permuted weight cols, contiguous).
// Per step: gates[16,512] = Ah[16,256] @ W_half via wmma (weights cp.async-
// staged, warp-private double buffer, exactly the R11 pipeline at half width),
// state update for the owned j-half, h written fp16 to BOTH CTAs' Ah[nbuf]
// (local store + st.shared::cluster), one barrier.cluster per step.
template <bool STORE_PAIR>
__global__ __launch_bounds__(RTHR, 1) __cluster_dims__(2, 1, 1)
void lstm_rec_tc2(const float* __restrict__ xp,    // [4][MTOT][256]
                  const __half* __restrict__ w2,   // [256][1024] permuted
                  const float* __restrict__ bp,    // [1024] orig order
                  __nv_bfloat16* __restrict__ ohi,
                  __nv_bfloat16* __restrict__ olo,
                  float* __restrict__ olast)       // [BATCH][HH]
{
    extern __shared__ __align__(16) char dsm[];
    __half* stgb  = (__half*)(dsm + STG_OFF);
    __half* Ahh   = (__half*)(dsm + AH_OFF);      // [2][16][264]
    float*  scr   = (float*)(dsm + SCR_OFF);      // [16][516]
    float*  sbias = (float*)(dsm + BIA_OFF);      // [512] (permuted n-local)

    const int tid  = threadIdx.x;
    const int wid  = tid >> 5;
    const int lane = tid & 31;
    uint32_t rank;
    asm("mov.u32 %0, %%cluster_ctarank;" : "=r"(rank));
    const int cl   = blockIdx.x >> 1;
    const int b0c  = cl * MB;

    const int n0l = wid * 32;                     // CTA-local n base (of 512)
    const int nW0 = (int)rank * 512 + n0l;        // packed weight col base
    const int b   = wid;                          // epilogue batch (=warp id)
    const int jl  = lane * 4;                     // epilogue j-local (4 j's)
    const int jg  = (int)rank * 128 + jl;         // global j

    __half* stg = stgb + wid * 2304;              // warp-private [2][16][72]
    uint32_t stg_u32;
    asm("{ .reg .u64 t; cvta.to.shared.u64 t, %1; cvt.u32.u64 %0, t; }"
        : "=r"(stg_u32) : "l"((const void*)stg));

#define PREF_W(kc_, buf_)                                                      \
    do {                                                                       \
        _Pragma("unroll")                                                      \
        for (int ii = 0; ii < 2; ++ii) {                                       \
            int op = ii * 32 + lane;                                           \
            int row = op >> 2, c16 = op & 3;                                   \
            uint32_t dst = stg_u32 + (buf_) * 2304 + row * 144 + c16 * 16;     \
            const void* src = (const void*)(w2 +                               \
                (size_t)((kc_) * 16 + row) * 1024 + nW0 + c16 * 8);            \
            asm volatile("cp.async.cg.shared.global [%0], [%1], 16;"           \
                         :: "r"(dst), "l"(src));                               \
        }                                                                      \
        asm volatile("cp.async.commit_group;" ::: "memory");                   \
    } while (0)

    // init: both Ah buffers zero; permuted bias for the owned 512 cols
    for (int i = tid; i < 2 * 16 * 264; i += RTHR) Ahh[i] = __float2half(0.0f);
    for (int i = tid; i < 512; i += RTHR) {
        int g = i >> 7, j = i & 127;
        sbias[i] = bp[g * 256 + (int)rank * 128 + j];
    }

    float c4[4];
#pragma unroll
    for (int v = 0; v < 4; ++v) c4[v] = 0.0f;

    PREF_W(0, 0);                                 // prime the pipeline
    __syncthreads();
    asm volatile("barrier.cluster.arrive.aligned;" ::: "memory");
    asm volatile("barrier.cluster.wait.aligned;" ::: "memory");

    for (int t = 0; t < TT; ++t) {
        const int buf  = t & 1;
        const int nbuf = buf ^ 1;
        const size_t m = (size_t)(b0c + b) * TT + t;

        // prefetch xp for (batch b, gates, jg..jg+3)
        float4 xg[4];
#pragma unroll
        for (int g = 0; g < 4; ++g)
            xg[g] = __ldg((const float4*)(xp + ((size_t)g * MTOT + m) * HH + jg));

        // ---- MMA: gates[16, n0l..n0l+32) over 16 k-chunks ----
        wmma::fragment<wmma::accumulator, 16, 16, 16, float> acc[2];
        wmma::fill_fragment(acc[0], 0.0f);
        wmma::fill_fragment(acc[1], 0.0f);

#pragma unroll 4
        for (int kc = 0; kc < 16; ++kc) {
            PREF_W((kc + 1) & 15, (kc + 1) & 1);
            asm volatile("cp.async.wait_group 1;" ::: "memory");
            __syncwarp();

            wmma::fragment<wmma::matrix_a, 16, 16, 16, __half,
                           wmma::row_major> fa;
            wmma::load_matrix_sync(fa, Ahh + buf * 4224 + kc * 16, 264);
            const __half* sb = stg + (kc & 1) * 1152;
#pragma unroll
            for (int f = 0; f < 2; ++f) {
                wmma::fragment<wmma::matrix_b, 16, 16, 16, __half,
                               wmma::row_major> fb;
                wmma::load_matrix_sync(fb, sb + f * 16, 72);
                wmma::mma_sync(acc[f], fa, fb, acc[f]);
            }
        }
#pragma unroll
        for (int f = 0; f < 2; ++f)
            wmma::store_matrix_sync(scr + n0l + f * 16, acc[f], 516,
                                    wmma::mem_row_major);
        __syncthreads();                          // scr visible CTA-wide

        // ---- state update: thread owns (batch b, jg..jg+3) ----
        float G[4][4];
#pragma unroll
        for (int g = 0; g < 4; ++g) {
            float4 sg = *(const float4*)&scr[b * 516 + g * 128 + jl];
            float4 bb = *(const float4*)&sbias[g * 128 + jl];
            G[g][0] = sg.x + bb.x + xg[g].x;
            G[g][1] = sg.y + bb.y + xg[g].y;
            G[g][2] = sg.z + bb.z + xg[g].z;
            G[g][3] = sg.w + bb.w + xg[g].w;
        }

        float hv[4];
#pragma unroll
        for (int v = 0; v < 4; ++v) {
            float iv = sig_ap(G[0][v]);
            float fv = sig_ap(G[1][v]);
            float gv = tanh_ap(G[2][v]);
            float ov = sig_ap(G[3][v]);
            c4[v] = fv * c4[v] + iv * gv;
            hv[v] = ov * tanh_ap(c4[v]);
        }

        // ---- h (fp16 x4 = 8B) -> local Ah[nbuf] and peer Ah[nbuf] ----
        {
            __half2 p0 = __floats2half2_rn(hv[0], hv[1]);
            __half2 p1 = __floats2half2_rn(hv[2], hv[3]);
            ull hd = (ull)(*(uint32_t*)&p0) | ((ull)(*(uint32_t*)&p1) << 32);
            __half* dst = Ahh + nbuf * 4224 + b * 264 + jg;
            *(ull*)dst = hd;
            uint32_t la, pa;
            asm("{ .reg .u64 t; cvta.to.shared.u64 t, %1; cvt.u32.u64 %0, t; }"
                : "=r"(la) : "l"((const void*)dst));
            asm("mapa.shared::cluster.u32 %0, %1, %2;"
                : "=r"(pa) : "r"(la), "r"(rank ^ 1u));
            asm volatile("st.shared::cluster.u64 [%0], %1;"
                         :: "r"(pa), "l"(hd) : "memory");
        }

        // outputs (gmem; do not touch Ah)
        if (STORE_PAIR) {
            __nv_bfloat162 h0 = __float22bfloat162_rn(make_float2(hv[0], hv[1]));
            __nv_bfloat162 h1 = __float22bfloat162_rn(make_float2(hv[2], hv[3]));
            float l0 = hv[0] - __bfloat162float(__low2bfloat16(h0));
            float l1 = hv[1] - __bfloat162float(__high2bfloat16(h0));
            float l2 = hv[2] - __bfloat162float(__low2bfloat16(h1));
            float l3 = hv[3] - __bfloat162float(__high2bfloat16(h1));
            __nv_bfloat162 q0 = __float22bfloat162_rn(make_float2(l0, l1));
            __nv_bfloat162 q1 = __float22bfloat162_rn(make_float2(l2, l3));
            *(uint2*)&ohi[m * HH + jg] = make_uint2(*(uint32_t*)&h0,
                                                    *(uint32_t*)&h1);
            *(uint2*)&olo[m * HH + jg] = make_uint2(*(uint32_t*)&q0,
                                                    *(uint32_t*)&q1);
        } else if (t == TT - 1) {
            *(float4*)&olast[(size_t)(b0c + b) * HH + jg] =
                make_float4(hv[0], hv[1], hv[2], hv[3]);
        }

        // ---- cluster barrier: all h writes (incl. DSMEM) visible ----
        asm volatile("barrier.cluster.arrive.aligned;" ::: "memory");
        asm volatile("barrier.cluster.wait.aligned;" ::: "memory");
    }
#undef PREF_W
}

// ---------------- LayerNorm + exact GELU + linear head ----------------------
__device__ __forceinline__ float block_sum_256(float v, float* red)
{
    __syncthreads();
#pragma unroll
    for (int o = 16; o > 0; o >>= 1) v += __shfl_down_sync(0xffffffffu, v, o);
    if ((threadIdx.x & 31) == 0) red[threadIdx.x >> 5] = v;
    __syncthreads();
    if (threadIdx.x < 8) {
        v = red[threadIdx.x];
#pragma unroll
        for (int o = 4; o > 0; o >>= 1) v += __shfl_down_sync(0xffu, v, o);
        if (threadIdx.x == 0) red[0] = v;
    }
    __syncthreads();
    return red[0];
}

__global__ __launch_bounds__(HH)
void head_kernel(const float* __restrict__ h2,
                 const float* __restrict__ gamma,
                 const float* __restrict__ beta,
                 const float* __restrict__ hw,
                 const float* __restrict__ hb,
                 float* __restrict__ outp)
{
    __shared__ float red[8];
    const int b = blockIdx.x;
    const int tid = threadIdx.x;

    float v  = h2[(size_t)b * HH + tid];
    float mu = block_sum_256(v, red) * (1.0f / HH);
    float d  = v - mu;
    float var = block_sum_256(d * d, red) * (1.0f / HH);
    float y  = d * rsqrtf(var + 1e-5f) * gamma[tid] + beta[tid];
    float gl = 0.5f * y * (1.0f + erff(y * 0.70710678118654752440f));
    float s  = block_sum_256(gl * hw[tid], red);
    if (tid == 0) outp[b] = s + hb[0];
}

// ---------------- launch ----------------------------------------------------
extern "C" void kernel_launch(void* const* d_in, const int* in_sizes, int n_in,
                              void* d_out, int out_size)
{
    (void)in_sizes; (void)n_in; (void)out_size;

    const float* x     = (const float*)d_in[0];
    const float* w_ih0 = (const float*)d_in[1];
    const float* w_hh0 = (const float*)d_in[2];
    const float* b_ih0 = (const float*)d_in[3];
    const float* b_hh0 = (const float*)d_in[4];
    const float* w_ih1 = (const float*)d_in[5];
    const float* w_hh1 = (const float*)d_in[6];
    const float* b_ih1 = (const float*)d_in[7];
    const float* b_hh1 = (const float*)d_in[8];
    const float* ln_g  = (const float*)d_in[9];
    const float* ln_b  = (const float*)d_in[10];
    const float* hw    = (const float*)d_in[11];
    const float* hb    = (const float*)d_in[12];
    float* outp = (float*)d_out;

    __nv_bfloat16 *xhi, *xlo, *w0hi, *w0lo, *w1hi, *w1lo, *h1hi, *h1lo;
    __half *w20, *w21;
    float *xp, *bp0, *bp1, *h2l;
    cudaGetSymbolAddress((void**)&xhi,  g_xhi);
    cudaGetSymbolAddress((void**)&xlo,  g_xlo);
    cudaGetSymbolAddress((void**)&w0hi, g_w0hi);
    cudaGetSymbolAddress((void**)&w0lo, g_w0lo);
    cudaGetSymbolAddress((void**)&w1hi, g_w1hi);
    cudaGetSymbolAddress((void**)&w1lo, g_w1lo);
    cudaGetSymbolAddress((void**)&h1hi, g_h1hi);
    cudaGetSymbolAddress((void**)&h1lo, g_h1lo);
    cudaGetSymbolAddress((void**)&xp,   g_xp);
    cudaGetSymbolAddress((void**)&w20,  g_w2_0);
    cudaGetSymbolAddress((void**)&w21,  g_w2_1);
    cudaGetSymbolAddress((void**)&bp0,  g_bias0);
    cudaGetSymbolAddress((void**)&bp1,  g_bias1);
    cudaGetSymbolAddress((void**)&h2l,  g_h2last);

    cudaFuncSetAttribute(gemm_xproj_smem<IIN>,
                         cudaFuncAttributeMaxDynamicSharedMemorySize, GEMM_SMEM);
    cudaFuncSetAttribute(gemm_xproj_smem<HH>,
                         cudaFuncAttributeMaxDynamicSharedMemorySize, GEMM_SMEM);
    cudaFuncSetAttribute(lstm_rec_tc2<true>,
                         cudaFuncAttributeMaxDynamicSharedMemorySize, REC_SMEM);
    cudaFuncSetAttribute(lstm_rec_tc2<false>,
                         cudaFuncAttributeMaxDynamicSharedMemorySize, REC_SMEM);

    cvt_pair_kernel<<<512, 256>>>(x,     xhi,  xlo,  (size_t)MTOT * IIN);
    cvt_pair_kernel<<<128, 256>>>(w_ih0, w0hi, w0lo, (size_t)4 * HH * IIN);
    pack_whh_tc<<<256, 256>>>(w_hh0, b_ih0, b_hh0, w20, bp0);
    pack_whh_tc<<<256, 256>>>(w_hh1, b_ih1, b_hh1, w21, bp1);

    // layer 0
    gemm_xproj_smem<IIN><<<dim3(MTOT / 128, 8), 256, GEMM_SMEM>>>(
        xhi, xlo, w0hi, w0lo, xp);
    lstm_rec_tc2<true><<<NCTA, RTHR, REC_SMEM>>>(xp, w20, bp0,
                                                 h1hi, h1lo, nullptr);

    // layer 1
    cvt_pair_kernel<<<256, 256>>>(w_ih1, w1hi, w1lo, (size_t)4 * HH * HH);
    gemm_xproj_smem<HH><<<dim3(MTOT / 128, 8), 256, GEMM_SMEM>>>(
        h1hi, h1lo, w1hi, w1lo, xp);
    lstm_rec_tc2<false><<<NCTA, RTHR, REC_SMEM>>>(xp, w21, bp1,
                                                  nullptr, nullptr, h2l);

    head_kernel<<<BATCH, HH>>>(h2l, ln_g, ln_b, hw, hb, outp);
}

// round 15
// speedup vs baseline: 2.1644x; 1.0661x over previous
#include <cuda_runtime.h>
#include <cuda_bf16.h>
#include <cuda_fp16.h>
#include <mma.h>
#include <math.h>
#include <stddef.h>
#include <stdint.h>

using namespace nvcuda;
typedef unsigned long long ull;

#define BATCH 512
#define TT    256
#define IIN   64
#define HH    256
#define MTOT  (BATCH * TT)          // 131072 rows for x_proj GEMMs

// GEMM staging
#define LDT        72               // padded smem ld (bf16 elems)
#define GEMM_SMEM  (4 * 128 * LDT * 2)      // 73728 B

// TC recurrence: 32 CTAs x 16 batches, 512 threads (16 warps x 64 N-cols)
#define MB       16
#define NCTA     (BATCH / MB)       // 32
#define RTHR     512
// smem: stage [16 warps][4 buf][16 k][72 n] half = 147456 B
//       Ah    [16 m][264 k] half                 =   8448 B
//       scr   [16 m][1044 n] f32                 =  66816 B
//       bias  [1032] f32                         =   4128 B
#define STG_BYTES   147456
#define A_OFF       STG_BYTES
#define A_BYTES     (16 * 264 * 2)
#define SCR_OFF     (A_OFF + A_BYTES)               // 155904
#define SCR_BYTES   (16 * 1044 * 4)
#define BIA_OFF     (SCR_OFF + SCR_BYTES)           // 222720
#define REC_SMEM    (BIA_OFF + 1032 * 4)            // 226848 B

// ---------------- static device scratch ------------------------------------
__device__ __nv_bfloat16 g_xhi[(size_t)MTOT * IIN];
__device__ __nv_bfloat16 g_xlo[(size_t)MTOT * IIN];
__device__ __nv_bfloat16 g_w0hi[4 * HH * IIN];
__device__ __nv_bfloat16 g_w0lo[4 * HH * IIN];
__device__ __nv_bfloat16 g_w1hi[4 * HH * HH];
__device__ __nv_bfloat16 g_w1lo[4 * HH * HH];
__device__ __nv_bfloat16 g_h1hi[(size_t)MTOT * HH];
__device__ __nv_bfloat16 g_h1lo[(size_t)MTOT * HH];
__device__ float  g_xp[(size_t)4 * MTOT * HH];    // [4][MTOT][256] gate-major
__device__ __half g_w2_0[HH * 4 * HH];            // k-major W^T [256][1024]
__device__ __half g_w2_1[HH * 4 * HH];
__device__ float  g_bias0[4 * HH];
__device__ float  g_bias1[4 * HH];
__device__ float  g_h2last[BATCH * HH];

__device__ __forceinline__ float tanh_ap(float x) {
    float y;
    asm("tanh.approx.f32 %0, %1;" : "=f"(y) : "f"(x));
    return y;
}
__device__ __forceinline__ float sig_ap(float x) {
    return 0.5f * tanh_ap(0.5f * x) + 0.5f;
}

// ---------------- conversions & packing ------------------------------------
__global__ void cvt_pair_kernel(const float* __restrict__ src,
                                __nv_bfloat16* __restrict__ hi,
                                __nv_bfloat16* __restrict__ lo, size_t n)
{
    for (size_t i = (size_t)blockIdx.x * blockDim.x + threadIdx.x; i < n;
         i += (size_t)gridDim.x * blockDim.x) {
        float v = src[i];
        __nv_bfloat16 h = __float2bfloat16(v);
        hi[i] = h;
        lo[i] = __float2bfloat16(v - __bfloat162float(h));
    }
}

// w_hh [1024 n][256 k] fp32 -> w2 [256 k][1024 n] fp16 (= W^T, k-major)
__global__ void pack_whh_tc(const float* __restrict__ w_hh,
                            const float* __restrict__ b_ih,
                            const float* __restrict__ b_hh,
                            __half* __restrict__ w2,
                            float* __restrict__ bp)
{
    for (int idx = blockIdx.x * blockDim.x + threadIdx.x; idx < 4 * HH * HH;
         idx += gridDim.x * blockDim.x) {
        int n = idx & 1023;
        int k = idx >> 10;
        w2[idx] = __float2half(w_hh[(size_t)n * HH + k]);
    }
    for (int r = blockIdx.x * blockDim.x + threadIdx.x; r < 4 * HH;
         r += gridDim.x * blockDim.x)
        bp[r] = b_ih[r] + b_hh[r];
}

// ---------------- x_proj GEMM: smem-staged HMMA (bf16 hi/lo 3-term) ----------
template <int K>
__global__ __launch_bounds__(256, 1)
void gemm_xproj_smem(const __nv_bfloat16* __restrict__ Ahi,
                     const __nv_bfloat16* __restrict__ Alo,
                     const __nv_bfloat16* __restrict__ Bhi,
                     const __nv_bfloat16* __restrict__ Blo,
                     float* __restrict__ xp)
{
    extern __shared__ __align__(16) __nv_bfloat16 sm[];
    __nv_bfloat16* sAhi = sm;
    __nv_bfloat16* sAlo = sm + 128 * LDT;
    __nv_bfloat16* sBhi = sm + 2 * 128 * LDT;
    __nv_bfloat16* sBlo = sm + 3 * 128 * LDT;

    const int tid = threadIdx.x;
    const int w   = tid >> 5;
    const int wm  = w & 3, wn = w >> 2;
    const size_t mBase = (size_t)blockIdx.x * 128;
    const int    nBase = blockIdx.y * 128;

    wmma::fragment<wmma::accumulator, 16, 16, 16, float> acc[2][4];
#pragma unroll
    for (int i = 0; i < 2; ++i)
#pragma unroll
        for (int f = 0; f < 4; ++f) wmma::fill_fragment(acc[i][f], 0.0f);

    for (int kc = 0; kc < K; kc += 64) {
        if (kc) __syncthreads();
        for (int i = tid; i < 1024; i += 256) {
            int row = i >> 3;
            int col = (i & 7) * 8;
            size_t ga = (mBase + row) * K + kc + col;
            size_t gb = ((size_t)(nBase + row)) * K + kc + col;
            *(uint4*)(sAhi + row * LDT + col) = *(const uint4*)(Ahi + ga);
            *(uint4*)(sAlo + row * LDT + col) = *(const uint4*)(Alo + ga);
            *(uint4*)(sBhi + row * LDT + col) = *(const uint4*)(Bhi + gb);
            *(uint4*)(sBlo + row * LDT + col) = *(const uint4*)(Blo + gb);
        }
        __syncthreads();

#pragma unroll
        for (int term = 0; term < 3; ++term) {
            const __nv_bfloat16* A = (term == 1) ? sAlo : sAhi;
            const __nv_bfloat16* B = (term == 2) ? sBlo : sBhi;
#pragma unroll
            for (int k0 = 0; k0 < 64; k0 += 16) {
                wmma::fragment<wmma::matrix_a, 16, 16, 16, __nv_bfloat16,
                               wmma::row_major> fa[2];
                wmma::load_matrix_sync(fa[0], A + (wm * 32) * LDT + k0, LDT);
                wmma::load_matrix_sync(fa[1], A + (wm * 32 + 16) * LDT + k0, LDT);
#pragma unroll
                for (int f = 0; f < 4; ++f) {
                    wmma::fragment<wmma::matrix_b, 16, 16, 16, __nv_bfloat16,
                                   wmma::col_major> fb;
                    wmma::load_matrix_sync(fb, B + (wn * 64 + f * 16) * LDT + k0,
                                           LDT);
                    wmma::mma_sync(acc[0][f], fa[0], fb, acc[0][f]);
                    wmma::mma_sync(acc[1][f], fa[1], fb, acc[1][f]);
                }
            }
        }
    }

    const size_t m0 = mBase + wm * 32;
    const int    n0 = nBase + wn * 64;
#pragma unroll
    for (int i = 0; i < 2; ++i)
#pragma unroll
        for (int f = 0; f < 4; ++f) {
            int c0 = n0 + f * 16;
            int g = c0 >> 8, j0 = c0 & 255;
            float* dst = xp + ((size_t)g * MTOT + m0 + i * 16) * HH + j0;
            wmma::store_matrix_sync(dst, acc[i][f], HH, wmma::mem_row_major);
        }
}

// ---------------- tensor-core recurrence (R11 + 4-buffer dist-2 pipeline) ----
// 32 CTAs x 16 batches. Per step: gates[16,1024] = Ah[16,256]@W^T via wmma,
// weights streamed through FOUR warp-private cp.async buffers, prefetch
// distance 2 (wait_group 2): two chunks of issue work cover the LDGSTS/L2
// latency that the old distance-1 pipeline left exposed. 16 % 4 == 0 so the
// chunk->buffer map (kc & 3) is identical every step.
template <bool STORE_PAIR>
__global__ __launch_bounds__(RTHR, 1)
void lstm_rec_tc(const float* __restrict__ xp,    // [4][MTOT][256]
                 const __half* __restrict__ w2,   // [256][1024] k-major
                 const float* __restrict__ bp,    // [1024]
                 __nv_bfloat16* __restrict__ ohi,
                 __nv_bfloat16* __restrict__ olo,
                 float* __restrict__ olast)       // [BATCH][HH]
{
    extern __shared__ __align__(16) char dsm[];
    __half* Ah    = (__half*)(dsm + A_OFF);       // [16][264]
    float*  scr   = (float*)(dsm + SCR_OFF);      // [16][1044]
    float*  sbias = (float*)(dsm + BIA_OFF);      // [1024]

    const int tid  = threadIdx.x;
    const int wid  = tid >> 5;
    const int lane = tid & 31;
    const int n0   = wid * 64;                    // warp's N-column base
    const int b    = wid;                         // epilogue batch == warp id
    const int j0e  = lane * 8;                    // epilogue j base (8 j's)
    const int b0c  = blockIdx.x * MB;

    __half* stg = (__half*)dsm + wid * 4608;      // warp-private [4][16][72]
    uint32_t stg_u32;
    asm("{ .reg .u64 t; cvta.to.shared.u64 t, %1; cvt.u32.u64 %0, t; }"
        : "=r"(stg_u32) : "l"((const void*)stg));

#define PREF_W(kc_, buf_)                                                      \
    do {                                                                       \
        _Pragma("unroll")                                                      \
        for (int ii = 0; ii < 4; ++ii) {                                       \
            int idx = ii * 32 + lane;                                          \
            int row = idx >> 3, col = (idx & 7) * 8;                           \
            uint32_t dst = stg_u32 + (buf_) * 2304 + row * 144 + col * 2;      \
            const void* src = (const void*)(w2 +                               \
                (size_t)((kc_) * 16 + row) * 1024 + n0 + col);                 \
            asm volatile("cp.async.cg.shared.global [%0], [%1], 16;"           \
                         :: "r"(dst), "l"(src));                               \
        }                                                                      \
        asm volatile("cp.async.commit_group;" ::: "memory");                   \
    } while (0)

    // init: A = 0, bias -> smem
    for (int i = tid; i < 16 * 264; i += RTHR) Ah[i] = __float2half(0.0f);
    for (int i = tid; i < 1024; i += RTHR) sbias[i] = bp[i];

    float c8[8];
#pragma unroll
    for (int v = 0; v < 8; ++v) c8[v] = 0.0f;

    PREF_W(0, 0);                                 // prime 2 chunks deep
    PREF_W(1, 1);
    __syncthreads();

    for (int t = 0; t < TT; ++t) {
        const size_t m = (size_t)(b0c + b) * TT + t;

        // prefetch xp for this thread's (b, j0e..j0e+8) — consumed after BAR_A
        float4 xg[4][2];
#pragma unroll
        for (int g = 0; g < 4; ++g) {
            const float* base = xp + ((size_t)g * MTOT + m) * HH + j0e;
            xg[g][0] = __ldg((const float4*)base);
            xg[g][1] = __ldg((const float4*)(base + 4));
        }

        // ---- MMA phase: 16 k-chunks, prefetch distance 2 ----
        wmma::fragment<wmma::accumulator, 16, 16, 16, float> acc[4];
#pragma unroll
        for (int f = 0; f < 4; ++f) wmma::fill_fragment(acc[f], 0.0f);

#pragma unroll 4
        for (int kc = 0; kc < 16; ++kc) {
            PREF_W((kc + 2) & 15, (kc + 2) & 3);
            asm volatile("cp.async.wait_group 2;" ::: "memory");
            __syncwarp();

            wmma::fragment<wmma::matrix_a, 16, 16, 16, __half,
                           wmma::row_major> fa;
            wmma::load_matrix_sync(fa, Ah + kc * 16, 264);
            const __half* sb = stg + (kc & 3) * 1152;
#pragma unroll
            for (int f = 0; f < 4; ++f) {
                wmma::fragment<wmma::matrix_b, 16, 16, 16, __half,
                               wmma::row_major> fb;
                wmma::load_matrix_sync(fb, sb + f * 16, 72);
                wmma::mma_sync(acc[f], fa, fb, acc[f]);
            }
        }

        // acc -> scratch
#pragma unroll
        for (int f = 0; f < 4; ++f)
            wmma::store_matrix_sync(scr + n0 + f * 16, acc[f], 1044,
                                    wmma::mem_row_major);
        __syncthreads();                          // BAR_A

        // ---- state update: thread owns (batch b, j0e..j0e+7) ----
        float G[4][8];
#pragma unroll
        for (int g = 0; g < 4; ++g) {
            const float* sp = scr + b * 1044 + g * 256 + j0e;
            float4 s0 = *(const float4*)sp;
            float4 s1 = *(const float4*)(sp + 4);
            float4 bb0 = *(const float4*)(sbias + g * 256 + j0e);
            float4 bb1 = *(const float4*)(sbias + g * 256 + j0e + 4);
            G[g][0] = s0.x + bb0.x + xg[g][0].x;
            G[g][1] = s0.y + bb0.y + xg[g][0].y;
            G[g][2] = s0.z + bb0.z + xg[g][0].z;
            G[g][3] = s0.w + bb0.w + xg[g][0].w;
            G[g][4] = s1.x + bb1.x + xg[g][1].x;
            G[g][5] = s1.y + bb1.y + xg[g][1].y;
            G[g][6] = s1.z + bb1.z + xg[g][1].z;
            G[g][7] = s1.w + bb1.w + xg[g][1].w;
        }

        float hv[8];
#pragma unroll
        for (int v = 0; v < 8; ++v) {
            float iv = sig_ap(G[0][v]);
            float fv = sig_ap(G[1][v]);
            float gv = tanh_ap(G[2][v]);
            float ov = sig_ap(G[3][v]);
            c8[v] = fv * c8[v] + iv * gv;
            hv[v] = ov * tanh_ap(c8[v]);
        }

        // h -> A smem (fp16)
        {
            __half2 p0 = __floats2half2_rn(hv[0], hv[1]);
            __half2 p1 = __floats2half2_rn(hv[2], hv[3]);
            __half2 p2 = __floats2half2_rn(hv[4], hv[5]);
            __half2 p3 = __floats2half2_rn(hv[6], hv[7]);
            uint4 pk = make_uint4(*(uint32_t*)&p0, *(uint32_t*)&p1,
                                  *(uint32_t*)&p2, *(uint32_t*)&p3);
            *(uint4*)&Ah[b * 264 + j0e] = pk;
        }

        // outputs
        if (STORE_PAIR) {
            __nv_bfloat162 h0 = __float22bfloat162_rn(make_float2(hv[0], hv[1]));
            __nv_bfloat162 h1 = __float22bfloat162_rn(make_float2(hv[2], hv[3]));
            __nv_bfloat162 h2 = __float22bfloat162_rn(make_float2(hv[4], hv[5]));
            __nv_bfloat162 h3 = __float22bfloat162_rn(make_float2(hv[6], hv[7]));
            float l[8];
            l[0] = hv[0] - __bfloat162float(__low2bfloat16(h0));
            l[1] = hv[1] - __bfloat162float(__high2bfloat16(h0));
            l[2] = hv[2] - __bfloat162float(__low2bfloat16(h1));
            l[3] = hv[3] - __bfloat162float(__high2bfloat16(h1));
            l[4] = hv[4] - __bfloat162float(__low2bfloat16(h2));
            l[5] = hv[5] - __bfloat162float(__high2bfloat16(h2));
            l[6] = hv[6] - __bfloat162float(__low2bfloat16(h3));
            l[7] = hv[7] - __bfloat162float(__high2bfloat16(h3));
            __nv_bfloat162 l0 = __float22bfloat162_rn(make_float2(l[0], l[1]));
            __nv_bfloat162 l1 = __float22bfloat162_rn(make_float2(l[2], l[3]));
            __nv_bfloat162 l2 = __float22bfloat162_rn(make_float2(l[4], l[5]));
            __nv_bfloat162 l3 = __float22bfloat162_rn(make_float2(l[6], l[7]));
            *(uint4*)&ohi[m * HH + j0e] =
                make_uint4(*(uint32_t*)&h0, *(uint32_t*)&h1,
                           *(uint32_t*)&h2, *(uint32_t*)&h3);
            *(uint4*)&olo[m * HH + j0e] =
                make_uint4(*(uint32_t*)&l0, *(uint32_t*)&l1,
                           *(uint32_t*)&l2, *(uint32_t*)&l3);
        } else if (t == TT - 1) {
            float* dst = olast + (size_t)(b0c + b) * HH + j0e;
            *(float4*)dst = make_float4(hv[0], hv[1], hv[2], hv[3]);
            *(float4*)(dst + 4) = make_float4(hv[4], hv[5], hv[6], hv[7]);
        }
        __syncthreads();                          // BAR_B
    }
#undef PREF_W
}

// ---------------- LayerNorm + exact GELU + linear head ----------------------
__device__ __forceinline__ float block_sum_256(float v, float* red)
{
    __syncthreads();
#pragma unroll
    for (int o = 16; o > 0; o >>= 1) v += __shfl_down_sync(0xffffffffu, v, o);
    if ((threadIdx.x & 31) == 0) red[threadIdx.x >> 5] = v;
    __syncthreads();
    if (threadIdx.x < 8) {
        v = red[threadIdx.x];
#pragma unroll
        for (int o = 4; o > 0; o >>= 1) v += __shfl_down_sync(0xffu, v, o);
        if (threadIdx.x == 0) red[0] = v;
    }
    __syncthreads();
    return red[0];
}

__global__ __launch_bounds__(HH)
void head_kernel(const float* __restrict__ h2,
                 const float* __restrict__ gamma,
                 const float* __restrict__ beta,
                 const float* __restrict__ hw,
                 const float* __restrict__ hb,
                 float* __restrict__ outp)
{
    __shared__ float red[8];
    const int b = blockIdx.x;
    const int tid = threadIdx.x;

    float v  = h2[(size_t)b * HH + tid];
    float mu = block_sum_256(v, red) * (1.0f / HH);
    float d  = v - mu;
    float var = block_sum_256(d * d, red) * (1.0f / HH);
    float y  = d * rsqrtf(var + 1e-5f) * gamma[tid] + beta[tid];
    float gl = 0.5f * y * (1.0f + erff(y * 0.70710678118654752440f));
    float s  = block_sum_256(gl * hw[tid], red);
    if (tid == 0) outp[b] = s + hb[0];
}

// ---------------- launch ----------------------------------------------------
extern "C" void kernel_launch(void* const* d_in, const int* in_sizes, int n_in,
                              void* d_out, int out_size)
{
    (void)in_sizes; (void)n_in; (void)out_size;

    const float* x     = (const float*)d_in[0];
    const float* w_ih0 = (const float*)d_in[1];
    const float* w_hh0 = (const float*)d_in[2];
    const float* b_ih0 = (const float*)d_in[3];
    const float* b_hh0 = (const float*)d_in[4];
    const float* w_ih1 = (const float*)d_in[5];
    const float* w_hh1 = (const float*)d_in[6];
    const float* b_ih1 = (const float*)d_in[7];
    const float* b_hh1 = (const float*)d_in[8];
    const float* ln_g  = (const float*)d_in[9];
    const float* ln_b  = (const float*)d_in[10];
    const float* hw    = (const float*)d_in[11];
    const float* hb    = (const float*)d_in[12];
    float* outp = (float*)d_out;

    __nv_bfloat16 *xhi, *xlo, *w0hi, *w0lo, *w1hi, *w1lo, *h1hi, *h1lo;
    __half *w20, *w21;
    float *xp, *bp0, *bp1, *h2l;
    cudaGetSymbolAddress((void**)&xhi,  g_xhi);
    cudaGetSymbolAddress((void**)&xlo,  g_xlo);
    cudaGetSymbolAddress((void**)&w0hi, g_w0hi);
    cudaGetSymbolAddress((void**)&w0lo, g_w0lo);
    cudaGetSymbolAddress((void**)&w1hi, g_w1hi);
    cudaGetSymbolAddress((void**)&w1lo, g_w1lo);
    cudaGetSymbolAddress((void**)&h1hi, g_h1hi);
    cudaGetSymbolAddress((void**)&h1lo, g_h1lo);
    cudaGetSymbolAddress((void**)&xp,   g_xp);
    cudaGetSymbolAddress((void**)&w20,  g_w2_0);
    cudaGetSymbolAddress((void**)&w21,  g_w2_1);
    cudaGetSymbolAddress((void**)&bp0,  g_bias0);
    cudaGetSymbolAddress((void**)&bp1,  g_bias1);
    cudaGetSymbolAddress((void**)&h2l,  g_h2last);

    cudaFuncSetAttribute(gemm_xproj_smem<IIN>,
                         cudaFuncAttributeMaxDynamicSharedMemorySize, GEMM_SMEM);
    cudaFuncSetAttribute(gemm_xproj_smem<HH>,
                         cudaFuncAttributeMaxDynamicSharedMemorySize, GEMM_SMEM);
    cudaFuncSetAttribute(lstm_rec_tc<true>,
                         cudaFuncAttributeMaxDynamicSharedMemorySize, REC_SMEM);
    cudaFuncSetAttribute(lstm_rec_tc<false>,
                         cudaFuncAttributeMaxDynamicSharedMemorySize, REC_SMEM);

    cvt_pair_kernel<<<512, 256>>>(x,     xhi,  xlo,  (size_t)MTOT * IIN);
    cvt_pair_kernel<<<128, 256>>>(w_ih0, w0hi, w0lo, (size_t)4 * HH * IIN);
    pack_whh_tc<<<256, 256>>>(w_hh0, b_ih0, b_hh0, w20, bp0);
    pack_whh_tc<<<256, 256>>>(w_hh1, b_ih1, b_hh1, w21, bp1);

    // layer 0
    gemm_xproj_smem<IIN><<<dim3(MTOT / 128, 8), 256, GEMM_SMEM>>>(
        xhi, xlo, w0hi, w0lo, xp);
    lstm_rec_tc<true><<<NCTA, RTHR, REC_SMEM>>>(xp, w20, bp0,
                                                h1hi, h1lo, nullptr);

    // layer 1
    cvt_pair_kernel<<<256, 256>>>(w_ih1, w1hi, w1lo, (size_t)4 * HH * HH);
    gemm_xproj_smem<HH><<<dim3(MTOT / 128, 8), 256, GEMM_SMEM>>>(
        h1hi, h1lo, w1hi, w1lo, xp);
    lstm_rec_tc<false><<<NCTA, RTHR, REC_SMEM>>>(xp, w21, bp1,
                                                 nullptr, nullptr, h2l);

    head_kernel<<<BATCH, HH>>>(h2l, ln_g, ln_b, hw, hb, outp);
}

// round 16
// speedup vs baseline: 2.2335x; 1.0319x over previous
#include <cuda_runtime.h>
#include <cuda_bf16.h>
#include <cuda_fp16.h>
#include <mma.h>
#include <math.h>
#include <stddef.h>
#include <stdint.h>

using namespace nvcuda;
typedef unsigned long long ull;

#define BATCH 512
#define TT    256
#define IIN   64
#define HH    256
#define MTOT  (BATCH * TT)          // 131072 rows for x_proj GEMMs

// GEMM staging
#define LDT        72               // padded smem ld (bf16 elems)
#define GEMM_SMEM  (4 * 128 * LDT * 2)      // 73728 B

// TC recurrence: 32 CTAs x 16 batches, 512 threads (16 warps x 64 N-cols)
#define MB       16
#define NCTA     (BATCH / MB)       // 32
#define RTHR     512
// smem: stage [16 warps][2 buf][16 k][72 n] half = 73728 B
//       Ah    [2 buf][16 m][264 k] half          = 16896 B
//       wscr  [16 warps][16 m][68 n] f32         = 69632 B
//       bias  [1024] f32 (permuted)              =  4096 B
#define STG_BYTES   73728
#define AH_OFF      STG_BYTES                       // 73728
#define AH_BYTES    (2 * 16 * 264 * 2)
#define SCR_OFF     (AH_OFF + AH_BYTES)             // 90624
#define SCR_BYTES   (16 * 16 * 68 * 4)
#define BIA_OFF     (SCR_OFF + SCR_BYTES)           // 160256
#define REC_SMEM    (BIA_OFF + 1024 * 4)            // 164352 B

// ---------------- static device scratch ------------------------------------
__device__ __nv_bfloat16 g_xhi[(size_t)MTOT * IIN];
__device__ __nv_bfloat16 g_xlo[(size_t)MTOT * IIN];
__device__ __nv_bfloat16 g_w0hi[4 * HH * IIN];
__device__ __nv_bfloat16 g_w0lo[4 * HH * IIN];
__device__ __nv_bfloat16 g_w1hi[4 * HH * HH];
__device__ __nv_bfloat16 g_w1lo[4 * HH * HH];
__device__ __nv_bfloat16 g_h1hi[(size_t)MTOT * HH];
__device__ __nv_bfloat16 g_h1lo[(size_t)MTOT * HH];
__device__ float  g_xp[(size_t)4 * MTOT * HH];    // [4][MTOT][256] gate-major
__device__ __half g_w2_0[HH * 4 * HH];   // permuted k-major W^T [256][1024]
__device__ __half g_w2_1[HH * 4 * HH];
__device__ float  g_bias0[4 * HH];
__device__ float  g_bias1[4 * HH];
__device__ float  g_h2last[BATCH * HH];

__device__ __forceinline__ float tanh_ap(float x) {
    float y;
    asm("tanh.approx.f32 %0, %1;" : "=f"(y) : "f"(x));
    return y;
}
__device__ __forceinline__ float sig_ap(float x) {
    return 0.5f * tanh_ap(0.5f * x) + 0.5f;
}

// ---------------- conversions & packing ------------------------------------
__global__ void cvt_pair_kernel(const float* __restrict__ src,
                                __nv_bfloat16* __restrict__ hi,
                                __nv_bfloat16* __restrict__ lo, size_t n)
{
    for (size_t i = (size_t)blockIdx.x * blockDim.x + threadIdx.x; i < n;
         i += (size_t)gridDim.x * blockDim.x) {
        float v = src[i];
        __nv_bfloat16 h = __float2bfloat16(v);
        hi[i] = h;
        lo[i] = __float2bfloat16(v - __bfloat162float(h));
    }
}

// w_hh [1024 n][256 k] fp32 -> w2 [256 k][1024 p] fp16, GATE-SLICED permute:
// packed col p -> j = (p>>6)*16 + (p&15), g = (p>>4)&3, orig n = g*256 + j.
// Warp w (cols [64w,64w+64)) thus owns ALL 4 gates for j in [16w,16w+16).
__global__ void pack_whh_tc(const float* __restrict__ w_hh,
                            const float* __restrict__ b_ih,
                            const float* __restrict__ b_hh,
                            __half* __restrict__ w2,
                            float* __restrict__ bp)   // bp permuted [1024]
{
    for (int idx = blockIdx.x * blockDim.x + threadIdx.x; idx < 4 * HH * HH;
         idx += gridDim.x * blockDim.x) {
        int p = idx & 1023;
        int k = idx >> 10;
        int j = ((p >> 6) << 4) + (p & 15);
        int g = (p >> 4) & 3;
        w2[idx] = __float2half(w_hh[(size_t)(g * 256 + j) * HH + k]);
    }
    for (int p = blockIdx.x * blockDim.x + threadIdx.x; p < 4 * HH;
         p += gridDim.x * blockDim.x) {
        int j = ((p >> 6) << 4) + (p & 15);
        int g = (p >> 4) & 3;
        int r = g * 256 + j;
        bp[p] = b_ih[r] + b_hh[r];
    }
}

// ---------------- x_proj GEMM: smem-staged HMMA (bf16 hi/lo 3-term) ----------
template <int K>
__global__ __launch_bounds__(256, 1)
void gemm_xproj_smem(const __nv_bfloat16* __restrict__ Ahi,
                     const __nv_bfloat16* __restrict__ Alo,
                     const __nv_bfloat16* __restrict__ Bhi,
                     const __nv_bfloat16* __restrict__ Blo,
                     float* __restrict__ xp)
{
    extern __shared__ __align__(16) __nv_bfloat16 sm[];
    __nv_bfloat16* sAhi = sm;
    __nv_bfloat16* sAlo = sm + 128 * LDT;
    __nv_bfloat16* sBhi = sm + 2 * 128 * LDT;
    __nv_bfloat16* sBlo = sm + 3 * 128 * LDT;

    const int tid = threadIdx.x;
    const int w   = tid >> 5;
    const int wm  = w & 3, wn = w >> 2;
    const size_t mBase = (size_t)blockIdx.x * 128;
    const int    nBase = blockIdx.y * 128;

    wmma::fragment<wmma::accumulator, 16, 16, 16, float> acc[2][4];
#pragma unroll
    for (int i = 0; i < 2; ++i)
#pragma unroll
        for (int f = 0; f < 4; ++f) wmma::fill_fragment(acc[i][f], 0.0f);

    for (int kc = 0; kc < K; kc += 64) {
        if (kc) __syncthreads();
        for (int i = tid; i < 1024; i += 256) {
            int row = i >> 3;
            int col = (i & 7) * 8;
            size_t ga = (mBase + row) * K + kc + col;
            size_t gb = ((size_t)(nBase + row)) * K + kc + col;
            *(uint4*)(sAhi + row * LDT + col) = *(const uint4*)(Ahi + ga);
            *(uint4*)(sAlo + row * LDT + col) = *(const uint4*)(Alo + ga);
            *(uint4*)(sBhi + row * LDT + col) = *(const uint4*)(Bhi + gb);
            *(uint4*)(sBlo + row * LDT + col) = *(const uint4*)(Blo + gb);
        }
        __syncthreads();

#pragma unroll
        for (int term = 0; term < 3; ++term) {
            const __nv_bfloat16* A = (term == 1) ? sAlo : sAhi;
            const __nv_bfloat16* B = (term == 2) ? sBlo : sBhi;
#pragma unroll
            for (int k0 = 0; k0 < 64; k0 += 16) {
                wmma::fragment<wmma::matrix_a, 16, 16, 16, __nv_bfloat16,
                               wmma::row_major> fa[2];
                wmma::load_matrix_sync(fa[0], A + (wm * 32) * LDT + k0, LDT);
                wmma::load_matrix_sync(fa[1], A + (wm * 32 + 16) * LDT + k0, LDT);
#pragma unroll
                for (int f = 0; f < 4; ++f) {
                    wmma::fragment<wmma::matrix_b, 16, 16, 16, __nv_bfloat16,
                                   wmma::col_major> fb;
                    wmma::load_matrix_sync(fb, B + (wn * 64 + f * 16) * LDT + k0,
                                           LDT);
                    wmma::mma_sync(acc[0][f], fa[0], fb, acc[0][f]);
                    wmma::mma_sync(acc[1][f], fa[1], fb, acc[1][f]);
                }
            }
        }
    }

    const size_t m0 = mBase + wm * 32;
    const int    n0 = nBase + wn * 64;
#pragma unroll
    for (int i = 0; i < 2; ++i)
#pragma unroll
        for (int f = 0; f < 4; ++f) {
            int c0 = n0 + f * 16;
            int g = c0 >> 8, j0 = c0 & 255;
            float* dst = xp + ((size_t)g * MTOT + m0 + i * 16) * HH + j0;
            wmma::store_matrix_sync(dst, acc[i][f], HH, wmma::mem_row_major);
        }
}

// ---------------- TC recurrence: warp-local epilogue, 1 barrier/step ---------
// 32 CTAs x 16 batches. Gate-sliced weight permutation means warp w's four
// acc fragments hold ALL 4 gates for j in [16w,16w+16) x all 16 batches:
// the acc->scratch->state-update path is warp-private (__syncwarp only).
// Ah is double-buffered so ONE __syncthreads per step suffices (h visibility
// + WAR). Weights stream via the proven R11 2-buffer warp-private cp.async.
template <bool STORE_PAIR>
__global__ __launch_bounds__(RTHR, 1)
void lstm_rec_tc(const float* __restrict__ xp,    // [4][MTOT][256]
                 const __half* __restrict__ w2,   // [256][1024] permuted
                 const float* __restrict__ bp,    // [1024] permuted
                 __nv_bfloat16* __restrict__ ohi,
                 __nv_bfloat16* __restrict__ olo,
                 float* __restrict__ olast)       // [BATCH][HH]
{
    extern __shared__ __align__(16) char dsm[];
    __half* Ahh   = (__half*)(dsm + AH_OFF);      // [2][16][264]
    float*  scrb  = (float*)(dsm + SCR_OFF);      // [16 warps][16][68]
    float*  sbias = (float*)(dsm + BIA_OFF);      // [1024] permuted

    const int tid  = threadIdx.x;
    const int wid  = tid >> 5;
    const int lane = tid & 31;
    const int n0   = wid * 64;                    // warp's packed col base
    const int b0c  = blockIdx.x * MB;

    const int mrow = lane >> 1;                   // batch row 0..15
    const int jj0  = (lane & 1) * 8;              // 8 j's within slice
    const int j0x  = wid * 16 + jj0;              // global j base
    const size_t mg = (size_t)(b0c + mrow);       // global batch

    float* wscr = scrb + wid * (16 * 68);         // warp-private [16][68]

    __half* stg = (__half*)dsm + wid * 2304;      // warp-private [2][16][72]
    uint32_t stg_u32;
    asm("{ .reg .u64 t; cvta.to.shared.u64 t, %1; cvt.u32.u64 %0, t; }"
        : "=r"(stg_u32) : "l"((const void*)stg));

#define PREF_W(kc_, buf_)                                                      \
    do {                                                                       \
        _Pragma("unroll")                                                      \
        for (int ii = 0; ii < 4; ++ii) {                                       \
            int idx = ii * 32 + lane;                                          \
            int row = idx >> 3, col = (idx & 7) * 8;                           \
            uint32_t dst = stg_u32 + (buf_) * 2304 + row * 144 + col * 2;      \
            const void* src = (const void*)(w2 +                               \
                (size_t)((kc_) * 16 + row) * 1024 + n0 + col);                 \
            asm volatile("cp.async.cg.shared.global [%0], [%1], 16;"           \
                         :: "r"(dst), "l"(src));                               \
        }                                                                      \
        asm volatile("cp.async.commit_group;" ::: "memory");                   \
    } while (0)

    // init: both Ah buffers zero; permuted bias -> smem
    for (int i = tid; i < 2 * 16 * 264; i += RTHR) Ahh[i] = __float2half(0.0f);
    for (int i = tid; i < 1024; i += RTHR) sbias[i] = bp[i];

    float c8[8];
#pragma unroll
    for (int v = 0; v < 8; ++v) c8[v] = 0.0f;

    PREF_W(0, 0);                                 // prime the pipeline
    __syncthreads();

    for (int t = 0; t < TT; ++t) {
        const int buf  = t & 1;
        const int nbuf = buf ^ 1;
        const size_t mo = mg * TT + t;

        // prefetch xp for (batch mrow, gates, j0x..j0x+7)
        float4 xg[4][2];
#pragma unroll
        for (int g = 0; g < 4; ++g) {
            const float* base = xp + ((size_t)g * MTOT + mo) * HH + j0x;
            xg[g][0] = __ldg((const float4*)base);
            xg[g][1] = __ldg((const float4*)(base + 4));
        }

        // ---- MMA phase: 16 k-chunks (R11 pipeline) ----
        wmma::fragment<wmma::accumulator, 16, 16, 16, float> acc[4];
#pragma unroll
        for (int f = 0; f < 4; ++f) wmma::fill_fragment(acc[f], 0.0f);

#pragma unroll 4
        for (int kc = 0; kc < 16; ++kc) {
            PREF_W((kc + 1) & 15, (kc + 1) & 1);
            asm volatile("cp.async.wait_group 1;" ::: "memory");
            __syncwarp();

            wmma::fragment<wmma::matrix_a, 16, 16, 16, __half,
                           wmma::row_major> fa;
            wmma::load_matrix_sync(fa, Ahh + buf * 4224 + kc * 16, 264);
            const __half* sb = stg + (kc & 1) * 1152;
#pragma unroll
            for (int f = 0; f < 4; ++f) {
                wmma::fragment<wmma::matrix_b, 16, 16, 16, __half,
                               wmma::row_major> fb;
                wmma::load_matrix_sync(fb, sb + f * 16, 72);
                wmma::mma_sync(acc[f], fa, fb, acc[f]);
            }
        }

        // acc -> WARP-PRIVATE scratch (no CTA barrier)
#pragma unroll
        for (int f = 0; f < 4; ++f)
            wmma::store_matrix_sync(wscr + f * 16, acc[f], 68,
                                    wmma::mem_row_major);
        __syncwarp();

        // ---- state update: thread owns (batch mrow, j0x..j0x+7) ----
        float G[4][8];
#pragma unroll
        for (int g = 0; g < 4; ++g) {
            const float* sp = wscr + mrow * 68 + g * 16 + jj0;
            float4 s0 = *(const float4*)sp;
            float4 s1 = *(const float4*)(sp + 4);
            const float* bb = sbias + wid * 64 + g * 16 + jj0;
            float4 b0 = *(const float4*)bb;
            float4 b1 = *(const float4*)(bb + 4);
            G[g][0] = s0.x + b0.x + xg[g][0].x;
            G[g][1] = s0.y + b0.y + xg[g][0].y;
            G[g][2] = s0.z + b0.z + xg[g][0].z;
            G[g][3] = s0.w + b0.w + xg[g][0].w;
            G[g][4] = s1.x + b1.x + xg[g][1].x;
            G[g][5] = s1.y + b1.y + xg[g][1].y;
            G[g][6] = s1.z + b1.z + xg[g][1].z;
            G[g][7] = s1.w + b1.w + xg[g][1].w;
        }

        float hv[8];
#pragma unroll
        for (int v = 0; v < 8; ++v) {
            float iv = sig_ap(G[0][v]);
            float fv = sig_ap(G[1][v]);
            float gv = tanh_ap(G[2][v]);
            float ov = sig_ap(G[3][v]);
            c8[v] = fv * c8[v] + iv * gv;
            hv[v] = ov * tanh_ap(c8[v]);
        }

        // h -> Ah[nbuf] (own j-slice, own batch row), fp16 x8 = 16B
        {
            __half2 p0 = __floats2half2_rn(hv[0], hv[1]);
            __half2 p1 = __floats2half2_rn(hv[2], hv[3]);
            __half2 p2 = __floats2half2_rn(hv[4], hv[5]);
            __half2 p3 = __floats2half2_rn(hv[6], hv[7]);
            uint4 pk = make_uint4(*(uint32_t*)&p0, *(uint32_t*)&p1,
                                  *(uint32_t*)&p2, *(uint32_t*)&p3);
            *(uint4*)&Ahh[nbuf * 4224 + mrow * 264 + j0x] = pk;
        }

        // outputs
        if (STORE_PAIR) {
            __nv_bfloat162 h0 = __float22bfloat162_rn(make_float2(hv[0], hv[1]));
            __nv_bfloat162 h1 = __float22bfloat162_rn(make_float2(hv[2], hv[3]));
            __nv_bfloat162 h2 = __float22bfloat162_rn(make_float2(hv[4], hv[5]));
            __nv_bfloat162 h3 = __float22bfloat162_rn(make_float2(hv[6], hv[7]));
            float l[8];
            l[0] = hv[0] - __bfloat162float(__low2bfloat16(h0));
            l[1] = hv[1] - __bfloat162float(__high2bfloat16(h0));
            l[2] = hv[2] - __bfloat162float(__low2bfloat16(h1));
            l[3] = hv[3] - __bfloat162float(__high2bfloat16(h1));
            l[4] = hv[4] - __bfloat162float(__low2bfloat16(h2));
            l[5] = hv[5] - __bfloat162float(__high2bfloat16(h2));
            l[6] = hv[6] - __bfloat162float(__low2bfloat16(h3));
            l[7] = hv[7] - __bfloat162float(__high2bfloat16(h3));
            __nv_bfloat162 l0 = __float22bfloat162_rn(make_float2(l[0], l[1]));
            __nv_bfloat162 l1 = __float22bfloat162_rn(make_float2(l[2], l[3]));
            __nv_bfloat162 l2 = __float22bfloat162_rn(make_float2(l[4], l[5]));
            __nv_bfloat162 l3 = __float22bfloat162_rn(make_float2(l[6], l[7]));
            *(uint4*)&ohi[mo * HH + j0x] =
                make_uint4(*(uint32_t*)&h0, *(uint32_t*)&h1,
                           *(uint32_t*)&h2, *(uint32_t*)&h3);
            *(uint4*)&olo[mo * HH + j0x] =
                make_uint4(*(uint32_t*)&l0, *(uint32_t*)&l1,
                           *(uint32_t*)&l2, *(uint32_t*)&l3);
        } else if (t == TT - 1) {
            float* dst = olast + mg * HH + j0x;
            *(float4*)dst = make_float4(hv[0], hv[1], hv[2], hv[3]);
            *(float4*)(dst + 4) = make_float4(hv[4], hv[5], hv[6], hv[7]);
        }

        __syncthreads();   // single barrier: Ah[nbuf] visible to all warps
    }
#undef PREF_W
}

// ---------------- LayerNorm + exact GELU + linear head ----------------------
__device__ __forceinline__ float block_sum_256(float v, float* red)
{
    __syncthreads();
#pragma unroll
    for (int o = 16; o > 0; o >>= 1) v += __shfl_down_sync(0xffffffffu, v, o);
    if ((threadIdx.x & 31) == 0) red[threadIdx.x >> 5] = v;
    __syncthreads();
    if (threadIdx.x < 8) {
        v = red[threadIdx.x];
#pragma unroll
        for (int o = 4; o > 0; o >>= 1) v += __shfl_down_sync(0xffu, v, o);
        if (threadIdx.x == 0) red[0] = v;
    }
    __syncthreads();
    return red[0];
}

__global__ __launch_bounds__(HH)
void head_kernel(const float* __restrict__ h2,
                 const float* __restrict__ gamma,
                 const float* __restrict__ beta,
                 const float* __restrict__ hw,
                 const float* __restrict__ hb,
                 float* __restrict__ outp)
{
    __shared__ float red[8];
    const int b = blockIdx.x;
    const int tid = threadIdx.x;

    float v  = h2[(size_t)b * HH + tid];
    float mu = block_sum_256(v, red) * (1.0f / HH);
    float d  = v - mu;
    float var = block_sum_256(d * d, red) * (1.0f / HH);
    float y  = d * rsqrtf(var + 1e-5f) * gamma[tid] + beta[tid];
    float gl = 0.5f * y * (1.0f + erff(y * 0.70710678118654752440f));
    float s  = block_sum_256(gl * hw[tid], red);
    if (tid == 0) outp[b] = s + hb[0];
}

// ---------------- launch ----------------------------------------------------
extern "C" void kernel_launch(void* const* d_in, const int* in_sizes, int n_in,
                              void* d_out, int out_size)
{
    (void)in_sizes; (void)n_in; (void)out_size;

    const float* x     = (const float*)d_in[0];
    const float* w_ih0 = (const float*)d_in[1];
    const float* w_hh0 = (const float*)d_in[2];
    const float* b_ih0 = (const float*)d_in[3];
    const float* b_hh0 = (const float*)d_in[4];
    const float* w_ih1 = (const float*)d_in[5];
    const float* w_hh1 = (const float*)d_in[6];
    const float* b_ih1 = (const float*)d_in[7];
    const float* b_hh1 = (const float*)d_in[8];
    const float* ln_g  = (const float*)d_in[9];
    const float* ln_b  = (const float*)d_in[10];
    const float* hw    = (const float*)d_in[11];
    const float* hb    = (const float*)d_in[12];
    float* outp = (float*)d_out;

    __nv_bfloat16 *xhi, *xlo, *w0hi, *w0lo, *w1hi, *w1lo, *h1hi, *h1lo;
    __half *w20, *w21;
    float *xp, *bp0, *bp1, *h2l;
    cudaGetSymbolAddress((void**)&xhi,  g_xhi);
    cudaGetSymbolAddress((void**)&xlo,  g_xlo);
    cudaGetSymbolAddress((void**)&w0hi, g_w0hi);
    cudaGetSymbolAddress((void**)&w0lo, g_w0lo);
    cudaGetSymbolAddress((void**)&w1hi, g_w1hi);
    cudaGetSymbolAddress((void**)&w1lo, g_w1lo);
    cudaGetSymbolAddress((void**)&h1hi, g_h1hi);
    cudaGetSymbolAddress((void**)&h1lo, g_h1lo);
    cudaGetSymbolAddress((void**)&xp,   g_xp);
    cudaGetSymbolAddress((void**)&w20,  g_w2_0);
    cudaGetSymbolAddress((void**)&w21,  g_w2_1);
    cudaGetSymbolAddress((void**)&bp0,  g_bias0);
    cudaGetSymbolAddress((void**)&bp1,  g_bias1);
    cudaGetSymbolAddress((void**)&h2l,  g_h2last);

    cudaFuncSetAttribute(gemm_xproj_smem<IIN>,
                         cudaFuncAttributeMaxDynamicSharedMemorySize, GEMM_SMEM);
    cudaFuncSetAttribute(gemm_xproj_smem<HH>,
                         cudaFuncAttributeMaxDynamicSharedMemorySize, GEMM_SMEM);
    cudaFuncSetAttribute(lstm_rec_tc<true>,
                         cudaFuncAttributeMaxDynamicSharedMemorySize, REC_SMEM);
    cudaFuncSetAttribute(lstm_rec_tc<false>,
                         cudaFuncAttributeMaxDynamicSharedMemorySize, REC_SMEM);

    cvt_pair_kernel<<<512, 256>>>(x,     xhi,  xlo,  (size_t)MTOT * IIN);
    cvt_pair_kernel<<<128, 256>>>(w_ih0, w0hi, w0lo, (size_t)4 * HH * IIN);
    pack_whh_tc<<<256, 256>>>(w_hh0, b_ih0, b_hh0, w20, bp0);
    pack_whh_tc<<<256, 256>>>(w_hh1, b_ih1, b_hh1, w21, bp1);

    // layer 0
    gemm_xproj_smem<IIN><<<dim3(MTOT / 128, 8), 256, GEMM_SMEM>>>(
        xhi, xlo, w0hi, w0lo, xp);
    lstm_rec_tc<true><<<NCTA, RTHR, REC_SMEM>>>(xp, w20, bp0,
                                                h1hi, h1lo, nullptr);

    // layer 1
    cvt_pair_kernel<<<256, 256>>>(w_ih1, w1hi, w1lo, (size_t)4 * HH * HH);
    gemm_xproj_smem<HH><<<dim3(MTOT / 128, 8), 256, GEMM_SMEM>>>(
        h1hi, h1lo, w1hi, w1lo, xp);
    lstm_rec_tc<false><<<NCTA, RTHR, REC_SMEM>>>(xp, w21, bp1,
                                                 nullptr, nullptr, h2l);

    head_kernel<<<BATCH, HH>>>(h2l, ln_g, ln_b, hw, hb, outp);
}

// round 17
// speedup vs baseline: 3.2625x; 1.4607x over previous
#include <cuda_runtime.h>
#include <cuda_bf16.h>
#include <cuda_fp16.h>
#include <mma.h>
#include <math.h>
#include <stddef.h>
#include <stdint.h>

using namespace nvcuda;
typedef unsigned long long ull;

#define BATCH 512
#define TT    256
#define IIN   64
#define HH    256
#define MTOT  (BATCH * TT)          // 131072 rows for x_proj GEMM (layer 0)

// GEMM staging
#define LDT        72               // padded smem ld (bf16 elems)
#define GEMM_SMEM  (4 * 128 * LDT * 2)      // 73728 B

// fused recurrence: 64 CTAs (32 layer-0 + 32 layer-1), 512 threads each
#define MB       16
#define RTHR     512
#define STG_BYTES   73728           // [16 warps][2 buf][16 k][72 n] half
// layer-0 layout (R11): Ah [16][264]h, scr [16][1044]f, bias [1024]f
#define A0_OFF      STG_BYTES                   // 73728
#define SCR0_OFF    (A0_OFF + 16 * 264 * 2)     // 82176
#define BIA0_OFF    (SCR0_OFF + 16 * 1044 * 4)  // 148992
// layer-1 layout: Ah [16][520]h (cols 0-255 h1_t, 256-511 h2_{t-1})
#define A1_OFF      STG_BYTES                   // 73728
#define SCR1_OFF    (A1_OFF + 16 * 520 * 2)     // 90368
#define BIA1_OFF    (SCR1_OFF + 16 * 1044 * 4)  // 157184
#define REC_SMEM    (BIA1_OFF + 1024 * 4)       // 161280 B

// ---------------- static device scratch ------------------------------------
__device__ __nv_bfloat16 g_xhi[(size_t)MTOT * IIN];
__device__ __nv_bfloat16 g_xlo[(size_t)MTOT * IIN];
__device__ __nv_bfloat16 g_w0hi[4 * HH * IIN];
__device__ __nv_bfloat16 g_w0lo[4 * HH * IIN];
__device__ float  g_xp[(size_t)4 * MTOT * HH];  // [4][MTOT][256] (layer 0)
__device__ __half g_w2_0[HH * 4 * HH];          // layer0 W_hh^T k-major
__device__ __half g_wcat[2 * HH * 4 * HH];      // layer1 [512 k][1024 n]
__device__ __half g_h1f[(size_t)MTOT * HH];     // h1 fp16 (producer->consumer)
__device__ float  g_bias0[4 * HH];
__device__ float  g_bias1[4 * HH];
__device__ float  g_h2last[BATCH * HH];
__device__ int    g_flags[32];                  // per-cluster step counters

__device__ __forceinline__ float tanh_ap(float x) {
    float y;
    asm("tanh.approx.f32 %0, %1;" : "=f"(y) : "f"(x));
    return y;
}
__device__ __forceinline__ float sig_ap(float x) {
    return 0.5f * tanh_ap(0.5f * x) + 0.5f;
}

// ---------------- conversions & packing ------------------------------------
__global__ void cvt_pair_kernel(const float* __restrict__ src,
                                __nv_bfloat16* __restrict__ hi,
                                __nv_bfloat16* __restrict__ lo, size_t n)
{
    for (size_t i = (size_t)blockIdx.x * blockDim.x + threadIdx.x; i < n;
         i += (size_t)gridDim.x * blockDim.x) {
        float v = src[i];
        __nv_bfloat16 h = __float2bfloat16(v);
        hi[i] = h;
        lo[i] = __float2bfloat16(v - __bfloat162float(h));
    }
}

// layer0: w_hh [1024 n][256 k] fp32 -> w2 [256 k][1024 n] fp16
__global__ void pack_whh_tc(const float* __restrict__ w_hh,
                            const float* __restrict__ b_ih,
                            const float* __restrict__ b_hh,
                            __half* __restrict__ w2,
                            float* __restrict__ bp)
{
    for (int idx = blockIdx.x * blockDim.x + threadIdx.x; idx < 4 * HH * HH;
         idx += gridDim.x * blockDim.x) {
        int n = idx & 1023;
        int k = idx >> 10;
        w2[idx] = __float2half(w_hh[(size_t)n * HH + k]);
    }
    for (int r = blockIdx.x * blockDim.x + threadIdx.x; r < 4 * HH;
         r += gridDim.x * blockDim.x)
        bp[r] = b_ih[r] + b_hh[r];
}

// layer1: wcat[k][n] = k<256 ? w_ih1[n][k] : w_hh1[n][k-256]; also zero flags.
__global__ void pack_wcat(const float* __restrict__ w_ih,
                          const float* __restrict__ w_hh,
                          const float* __restrict__ b_ih,
                          const float* __restrict__ b_hh,
                          __half* __restrict__ wc,
                          float* __restrict__ bp,
                          int* __restrict__ flags)
{
    for (int idx = blockIdx.x * blockDim.x + threadIdx.x; idx < 8 * HH * HH;
         idx += gridDim.x * blockDim.x) {
        int n = idx & 1023;
        int k = idx >> 10;
        float v = (k < HH) ? w_ih[(size_t)n * HH + k]
                           : w_hh[(size_t)n * HH + (k - HH)];
        wc[idx] = __float2half(v);
    }
    for (int r = blockIdx.x * blockDim.x + threadIdx.x; r < 4 * HH;
         r += gridDim.x * blockDim.x)
        bp[r] = b_ih[r] + b_hh[r];
    if (blockIdx.x == 0 && threadIdx.x < 32) flags[threadIdx.x] = 0;
}

// ---------------- x_proj GEMM for layer 0 (bf16 hi/lo 3-term) ----------------
template <int K>
__global__ __launch_bounds__(256, 1)
void gemm_xproj_smem(const __nv_bfloat16* __restrict__ Ahi,
                     const __nv_bfloat16* __restrict__ Alo,
                     const __nv_bfloat16* __restrict__ Bhi,
                     const __nv_bfloat16* __restrict__ Blo,
                     float* __restrict__ xp)
{
    extern __shared__ __align__(16) __nv_bfloat16 sm[];
    __nv_bfloat16* sAhi = sm;
    __nv_bfloat16* sAlo = sm + 128 * LDT;
    __nv_bfloat16* sBhi = sm + 2 * 128 * LDT;
    __nv_bfloat16* sBlo = sm + 3 * 128 * LDT;

    const int tid = threadIdx.x;
    const int w   = tid >> 5;
    const int wm  = w & 3, wn = w >> 2;
    const size_t mBase = (size_t)blockIdx.x * 128;
    const int    nBase = blockIdx.y * 128;

    wmma::fragment<wmma::accumulator, 16, 16, 16, float> acc[2][4];
#pragma unroll
    for (int i = 0; i < 2; ++i)
#pragma unroll
        for (int f = 0; f < 4; ++f) wmma::fill_fragment(acc[i][f], 0.0f);

    for (int kc = 0; kc < K; kc += 64) {
        if (kc) __syncthreads();
        for (int i = tid; i < 1024; i += 256) {
            int row = i >> 3;
            int col = (i & 7) * 8;
            size_t ga = (mBase + row) * K + kc + col;
            size_t gb = ((size_t)(nBase + row)) * K + kc + col;
            *(uint4*)(sAhi + row * LDT + col) = *(const uint4*)(Ahi + ga);
            *(uint4*)(sAlo + row * LDT + col) = *(const uint4*)(Alo + ga);
            *(uint4*)(sBhi + row * LDT + col) = *(const uint4*)(Bhi + gb);
            *(uint4*)(sBlo + row * LDT + col) = *(const uint4*)(Blo + gb);
        }
        __syncthreads();

#pragma unroll
        for (int term = 0; term < 3; ++term) {
            const __nv_bfloat16* A = (term == 1) ? sAlo : sAhi;
            const __nv_bfloat16* B = (term == 2) ? sBlo : sBhi;
#pragma unroll
            for (int k0 = 0; k0 < 64; k0 += 16) {
                wmma::fragment<wmma::matrix_a, 16, 16, 16, __nv_bfloat16,
                               wmma::row_major> fa[2];
                wmma::load_matrix_sync(fa[0], A + (wm * 32) * LDT + k0, LDT);
                wmma::load_matrix_sync(fa[1], A + (wm * 32 + 16) * LDT + k0, LDT);
#pragma unroll
                for (int f = 0; f < 4; ++f) {
                    wmma::fragment<wmma::matrix_b, 16, 16, 16, __nv_bfloat16,
                                   wmma::col_major> fb;
                    wmma::load_matrix_sync(fb, B + (wn * 64 + f * 16) * LDT + k0,
                                           LDT);
                    wmma::mma_sync(acc[0][f], fa[0], fb, acc[0][f]);
                    wmma::mma_sync(acc[1][f], fa[1], fb, acc[1][f]);
                }
            }
        }
    }

    const size_t m0 = mBase + wm * 32;
    const int    n0 = nBase + wn * 64;
#pragma unroll
    for (int i = 0; i < 2; ++i)
#pragma unroll
        for (int f = 0; f < 4; ++f) {
            int c0 = n0 + f * 16;
            int g = c0 >> 8, j0 = c0 & 255;
            float* dst = xp + ((size_t)g * MTOT + m0 + i * 16) * HH + j0;
            wmma::store_matrix_sync(dst, acc[i][f], HH, wmma::mem_row_major);
        }
}

// ---------------- fused 2-layer pipelined recurrence -------------------------
// 64 CTAs. Blocks 0-31: layer-0 recurrence (R11 path), emit h1 fp16 + release
// flags[cl] = t+1. Blocks 32-63: layer-1 with fused x-projection:
// gates[16,1024] = [h1_t | h2_{t-1}][16,512] @ Wcat^T, consuming h1 via
// acquire-spin on flags. Layer 0 runs ~1.6x faster per step, so layer-1 spins
// hit the fast path; total time ~= layer-1 time (GEMM<256> stage eliminated).
__global__ __launch_bounds__(RTHR, 1)
void lstm_fused(const float* __restrict__ xp,     // [4][MTOT][256] (layer 0)
                const __half* __restrict__ w2,    // [256][1024] layer0
                const __half* __restrict__ wcat,  // [512][1024] layer1
                const float* __restrict__ bp0,    // [1024]
                const float* __restrict__ bp1,    // [1024]
                __half* __restrict__ h1f,         // [MTOT][256] fp16
                int* __restrict__ flags,          // [32]
                float* __restrict__ olast)        // [BATCH][HH]
{
    extern __shared__ __align__(16) char dsm[];
    const int tid  = threadIdx.x;
    const int wid  = tid >> 5;
    const int lane = tid & 31;
    const int role = blockIdx.x >> 5;             // 0 = layer0, 1 = layer1
    const int cl   = blockIdx.x & 31;
    const int n0   = wid * 64;
    const int b    = wid;                         // epilogue batch == warp id
    const int j0e  = lane * 8;
    const int b0c  = cl * MB;

    __half* stg = (__half*)dsm + wid * 2304;      // warp-private [2][16][72]
    uint32_t stg_u32;
    asm("{ .reg .u64 t; cvta.to.shared.u64 t, %1; cvt.u32.u64 %0, t; }"
        : "=r"(stg_u32) : "l"((const void*)stg));

    float c8[8];
#pragma unroll
    for (int v = 0; v < 8; ++v) c8[v] = 0.0f;

#define PREF_W(SRC, kc_, buf_)                                                 \
    do {                                                                       \
        _Pragma("unroll")                                                      \
        for (int ii = 0; ii < 4; ++ii) {                                       \
            int idx = ii * 32 + lane;                                          \
            int row = idx >> 3, col = (idx & 7) * 8;                           \
            uint32_t dst = stg_u32 + (buf_) * 2304 + row * 144 + col * 2;      \
            const void* src = (const void*)((SRC) +                            \
                (size_t)((kc_) * 16 + row) * 1024 + n0 + col);                 \
            asm volatile("cp.async.cg.shared.global [%0], [%1], 16;"           \
                         :: "r"(dst), "l"(src));                               \
        }                                                                      \
        asm volatile("cp.async.commit_group;" ::: "memory");                   \
    } while (0)

#define EPILOGUE_GATES(SCR, SBIA, XADD)                                        \
    float G[4][8];                                                             \
    _Pragma("unroll")                                                          \
    for (int g = 0; g < 4; ++g) {                                              \
        const float* sp = (SCR) + b * 1044 + g * 256 + j0e;                    \
        float4 s0 = *(const float4*)sp;                                        \
        float4 s1 = *(const float4*)(sp + 4);                                  \
        float4 bb0 = *(const float4*)((SBIA) + g * 256 + j0e);                 \
        float4 bb1 = *(const float4*)((SBIA) + g * 256 + j0e + 4);             \
        G[g][0] = s0.x + bb0.x + XADD(g, 0);                                   \
        G[g][1] = s0.y + bb0.y + XADD(g, 1);                                   \
        G[g][2] = s0.z + bb0.z + XADD(g, 2);                                   \
        G[g][3] = s0.w + bb0.w + XADD(g, 3);                                   \
        G[g][4] = s1.x + bb1.x + XADD(g, 4);                                   \
        G[g][5] = s1.y + bb1.y + XADD(g, 5);                                   \
        G[g][6] = s1.z + bb1.z + XADD(g, 6);                                   \
        G[g][7] = s1.w + bb1.w + XADD(g, 7);                                   \
    }                                                                          \
    float hv[8];                                                               \
    _Pragma("unroll")                                                          \
    for (int v = 0; v < 8; ++v) {                                              \
        float iv = sig_ap(G[0][v]);                                            \
        float fv = sig_ap(G[1][v]);                                            \
        float gv = tanh_ap(G[2][v]);                                           \
        float ov = sig_ap(G[3][v]);                                            \
        c8[v] = fv * c8[v] + iv * gv;                                          \
        hv[v] = ov * tanh_ap(c8[v]);                                           \
    }

    if (role == 0) {
        // =================== layer 0 (producer) ===========================
        __half* Ah    = (__half*)(dsm + A0_OFF);      // [16][264]
        float*  scr   = (float*)(dsm + SCR0_OFF);     // [16][1044]
        float*  sbias = (float*)(dsm + BIA0_OFF);

        for (int i = tid; i < 16 * 264; i += RTHR) Ah[i] = __float2half(0.0f);
        for (int i = tid; i < 1024; i += RTHR) sbias[i] = bp0[i];

        PREF_W(w2, 0, 0);
        __syncthreads();

        for (int t = 0; t < TT; ++t) {
            const size_t mo = ((size_t)(b0c + b) * TT + t);

            float4 xg[4][2];
#pragma unroll
            for (int g = 0; g < 4; ++g) {
                const float* base = xp + ((size_t)g * MTOT + mo) * HH + j0e;
                xg[g][0] = __ldg((const float4*)base);
                xg[g][1] = __ldg((const float4*)(base + 4));
            }

            wmma::fragment<wmma::accumulator, 16, 16, 16, float> acc[4];
#pragma unroll
            for (int f = 0; f < 4; ++f) wmma::fill_fragment(acc[f], 0.0f);

#pragma unroll 4
            for (int kc = 0; kc < 16; ++kc) {
                PREF_W(w2, (kc + 1) & 15, (kc + 1) & 1);
                asm volatile("cp.async.wait_group 1;" ::: "memory");
                __syncwarp();
                wmma::fragment<wmma::matrix_a, 16, 16, 16, __half,
                               wmma::row_major> fa;
                wmma::load_matrix_sync(fa, Ah + kc * 16, 264);
                const __half* sb = stg + (kc & 1) * 1152;
#pragma unroll
                for (int f = 0; f < 4; ++f) {
                    wmma::fragment<wmma::matrix_b, 16, 16, 16, __half,
                                   wmma::row_major> fb;
                    wmma::load_matrix_sync(fb, sb + f * 16, 72);
                    wmma::mma_sync(acc[f], fa, fb, acc[f]);
                }
            }
#pragma unroll
            for (int f = 0; f < 4; ++f)
                wmma::store_matrix_sync(scr + n0 + f * 16, acc[f], 1044,
                                        wmma::mem_row_major);
            __syncthreads();                      // BAR_A

#define XG0(g, v) (xg[g][(v) >> 2].x * 0.f + ((const float*)&xg[g][(v) >> 2])[(v) & 3])
            EPILOGUE_GATES(scr, sbias, XG0)
#undef XG0

            __half2 p0 = __floats2half2_rn(hv[0], hv[1]);
            __half2 p1 = __floats2half2_rn(hv[2], hv[3]);
            __half2 p2 = __floats2half2_rn(hv[4], hv[5]);
            __half2 p3 = __floats2half2_rn(hv[6], hv[7]);
            uint4 pk = make_uint4(*(uint32_t*)&p0, *(uint32_t*)&p1,
                                  *(uint32_t*)&p2, *(uint32_t*)&p3);
            *(uint4*)&Ah[b * 264 + j0e] = pk;
            *(uint4*)&h1f[mo * HH + j0e] = pk;    // publish h1 (fp16)

            __syncthreads();                      // BAR_B: h writes done
            if (tid == 0)
                asm volatile("st.release.gpu.global.b32 [%0], %1;"
                             :: "l"(flags + cl), "r"(t + 1) : "memory");
        }
    } else {
        // =================== layer 1 (consumer, fused x-proj) =============
        __half* Ah    = (__half*)(dsm + A1_OFF);      // [16][520]
        float*  scr   = (float*)(dsm + SCR1_OFF);     // [16][1044]
        float*  sbias = (float*)(dsm + BIA1_OFF);

        for (int i = tid; i < 16 * 520; i += RTHR) Ah[i] = __float2half(0.0f);
        for (int i = tid; i < 1024; i += RTHR) sbias[i] = bp1[i];

        PREF_W(wcat, 0, 0);
        __syncthreads();

        for (int t = 0; t < TT; ++t) {
            // wait for h1_t, then load it into Ah[:, 0:256]
            if (tid == 0) {
                int f;
                do {
                    asm volatile("ld.acquire.gpu.global.b32 %0, [%1];"
                                 : "=r"(f) : "l"(flags + cl) : "memory");
                } while (f < t + 1);
            }
            __syncthreads();                      // BAR_0: flag observed
            {   // warp w loads batch w's 256 halfs (512 B, coalesced)
                const __half* src =
                    h1f + ((size_t)(b0c + wid) * TT + t) * HH + lane * 8;
                *(uint4*)&Ah[wid * 520 + lane * 8] = *(const uint4*)src;
            }
            __syncthreads();                      // BAR_1: Ah h1 part ready

            wmma::fragment<wmma::accumulator, 16, 16, 16, float> acc[4];
#pragma unroll
            for (int f = 0; f < 4; ++f) wmma::fill_fragment(acc[f], 0.0f);

#pragma unroll 4
            for (int kc = 0; kc < 32; ++kc) {
                PREF_W(wcat, (kc + 1) & 31, (kc + 1) & 1);
                asm volatile("cp.async.wait_group 1;" ::: "memory");
                __syncwarp();
                wmma::fragment<wmma::matrix_a, 16, 16, 16, __half,
                               wmma::row_major> fa;
                wmma::load_matrix_sync(fa, Ah + kc * 16, 520);
                const __half* sb = stg + (kc & 1) * 1152;
#pragma unroll
                for (int f = 0; f < 4; ++f) {
                    wmma::fragment<wmma::matrix_b, 16, 16, 16, __half,
                                   wmma::row_major> fb;
                    wmma::load_matrix_sync(fb, sb + f * 16, 72);
                    wmma::mma_sync(acc[f], fa, fb, acc[f]);
                }
            }
#pragma unroll
            for (int f = 0; f < 4; ++f)
                wmma::store_matrix_sync(scr + n0 + f * 16, acc[f], 1044,
                                        wmma::mem_row_major);
            __syncthreads();                      // BAR_A

#define XG1(g, v) 0.0f
            EPILOGUE_GATES(scr, sbias, XG1)
#undef XG1

            __half2 p0 = __floats2half2_rn(hv[0], hv[1]);
            __half2 p1 = __floats2half2_rn(hv[2], hv[3]);
            __half2 p2 = __floats2half2_rn(hv[4], hv[5]);
            __half2 p3 = __floats2half2_rn(hv[6], hv[7]);
            uint4 pk = make_uint4(*(uint32_t*)&p0, *(uint32_t*)&p1,
                                  *(uint32_t*)&p2, *(uint32_t*)&p3);
            *(uint4*)&Ah[b * 520 + 256 + j0e] = pk;   // h2 -> concat region

            if (t == TT - 1) {
                float* dst = olast + (size_t)(b0c + b) * HH + j0e;
                *(float4*)dst = make_float4(hv[0], hv[1], hv[2], hv[3]);
                *(float4*)(dst + 4) = make_float4(hv[4], hv[5], hv[6], hv[7]);
            }
            __syncthreads();                      // BAR_B
        }
    }
#undef PREF_W
#undef EPILOGUE_GATES
}

// ---------------- LayerNorm + exact GELU + linear head ----------------------
__device__ __forceinline__ float block_sum_256(float v, float* red)
{
    __syncthreads();
#pragma unroll
    for (int o = 16; o > 0; o >>= 1) v += __shfl_down_sync(0xffffffffu, v, o);
    if ((threadIdx.x & 31) == 0) red[threadIdx.x >> 5] = v;
    __syncthreads();
    if (threadIdx.x < 8) {
        v = red[threadIdx.x];
#pragma unroll
        for (int o = 4; o > 0; o >>= 1) v += __shfl_down_sync(0xffu, v, o);
        if (threadIdx.x == 0) red[0] = v;
    }
    __syncthreads();
    return red[0];
}

__global__ __launch_bounds__(HH)
void head_kernel(const float* __restrict__ h2,
                 const float* __restrict__ gamma,
                 const float* __restrict__ beta,
                 const float* __restrict__ hw,
                 const float* __restrict__ hb,
                 float* __restrict__ outp)
{
    __shared__ float red[8];
    const int b = blockIdx.x;
    const int tid = threadIdx.x;

    float v  = h2[(size_t)b * HH + tid];
    float mu = block_sum_256(v, red) * (1.0f / HH);
    float d  = v - mu;
    float var = block_sum_256(d * d, red) * (1.0f / HH);
    float y  = d * rsqrtf(var + 1e-5f) * gamma[tid] + beta[tid];
    float gl = 0.5f * y * (1.0f + erff(y * 0.70710678118654752440f));
    float s  = block_sum_256(gl * hw[tid], red);
    if (tid == 0) outp[b] = s + hb[0];
}

// ---------------- launch ----------------------------------------------------
extern "C" void kernel_launch(void* const* d_in, const int* in_sizes, int n_in,
                              void* d_out, int out_size)
{
    (void)in_sizes; (void)n_in; (void)out_size;

    const float* x     = (const float*)d_in[0];
    const float* w_ih0 = (const float*)d_in[1];
    const float* w_hh0 = (const float*)d_in[2];
    const float* b_ih0 = (const float*)d_in[3];
    const float* b_hh0 = (const float*)d_in[4];
    const float* w_ih1 = (const float*)d_in[5];
    const float* w_hh1 = (const float*)d_in[6];
    const float* b_ih1 = (const float*)d_in[7];
    const float* b_hh1 = (const float*)d_in[8];
    const float* ln_g  = (const float*)d_in[9];
    const float* ln_b  = (const float*)d_in[10];
    const float* hw    = (const float*)d_in[11];
    const float* hb    = (const float*)d_in[12];
    float* outp = (float*)d_out;

    __nv_bfloat16 *xhi, *xlo, *w0hi, *w0lo;
    __half *w20, *wcat, *h1f;
    float *xp, *bp0, *bp1, *h2l;
    int* flags;
    cudaGetSymbolAddress((void**)&xhi,   g_xhi);
    cudaGetSymbolAddress((void**)&xlo,   g_xlo);
    cudaGetSymbolAddress((void**)&w0hi,  g_w0hi);
    cudaGetSymbolAddress((void**)&w0lo,  g_w0lo);
    cudaGetSymbolAddress((void**)&xp,    g_xp);
    cudaGetSymbolAddress((void**)&w20,   g_w2_0);
    cudaGetSymbolAddress((void**)&wcat,  g_wcat);
    cudaGetSymbolAddress((void**)&h1f,   g_h1f);
    cudaGetSymbolAddress((void**)&bp0,   g_bias0);
    cudaGetSymbolAddress((void**)&bp1,   g_bias1);
    cudaGetSymbolAddress((void**)&h2l,   g_h2last);
    cudaGetSymbolAddress((void**)&flags, g_flags);

    cudaFuncSetAttribute(gemm_xproj_smem<IIN>,
                         cudaFuncAttributeMaxDynamicSharedMemorySize, GEMM_SMEM);
    cudaFuncSetAttribute(lstm_fused,
                         cudaFuncAttributeMaxDynamicSharedMemorySize, REC_SMEM);

    cvt_pair_kernel<<<512, 256>>>(x,     xhi,  xlo,  (size_t)MTOT * IIN);
    cvt_pair_kernel<<<128, 256>>>(w_ih0, w0hi, w0lo, (size_t)4 * HH * IIN);
    pack_whh_tc<<<256, 256>>>(w_hh0, b_ih0, b_hh0, w20, bp0);
    pack_wcat<<<256, 256>>>(w_ih1, w_hh1, b_ih1, b_hh1, wcat, bp1, flags);

    gemm_xproj_smem<IIN><<<dim3(MTOT / 128, 8), 256, GEMM_SMEM>>>(
        xhi, xlo, w0hi, w0lo, xp);

    lstm_fused<<<64, RTHR, REC_SMEM>>>(xp, w20, wcat, bp0, bp1,
                                       h1f, flags, h2l);

    head_kernel<<<BATCH, HH>>>(h2l, ln_g, ln_b, hw, hb, outp);
}